// round 5
// baseline (speedup 1.0000x reference)
#include <cuda_runtime.h>
#include <cuda_fp16.h>
#include <math.h>

// Problem constants
#define BB   8
#define SEQ  4096
#define CDIM 512
#define NH   8
#define HD   64
#define MROWS (BB*SEQ)   // 32768
#define NBH  (BB*NH)     // 64
#define KVCH 8           // seq chunks for KV partials (4096/512)

// ---------------- static device scratch (total ~42 MB) --------------------
__device__ float  g_KV_part[KVCH][NBH][HD][HD];   // 8.4 MB
__device__ float  g_Ksum_part[KVCH][NBH][HD];     // 128 KB
__device__ float  g_KV[NBH][HD][HD];              // 1 MB
__device__ float  g_Ksum[NBH][HD];                // 16 KB
__device__ __half g_attnh[(size_t)MROWS*CDIM];    // 32 MB

__device__ __forceinline__ float phi_map(float x) {
    return x > 0.0f ? x + 1.0f : __expf(x);
}
__device__ __forceinline__ float f4c(const float4 v, int i) {
    return (i == 0) ? v.x : (i == 1) ? v.y : (i == 2) ? v.z : v.w;
}
__device__ __forceinline__ void fma4(float4& a, float s, const float4 b) {
    a.x += s * b.x; a.y += s * b.y; a.z += s * b.z; a.w += s * b.w;
}

// ===========================================================================
// K1: fused KV builder.  Block = (bh, chunk of 512 tokens).
// Computes k,v = x @ Wk|Wv on the fly (fp32), applies phi to k, accumulates
// KV[d][e] += kphi[n][d]*v[n][e] and Ksum[d] over its 512 tokens.
// ===========================================================================
__global__ __launch_bounds__(256)
void kv_build_kernel(const float* __restrict__ x,
                     const float* __restrict__ Wqkv)
{
    __shared__ alignas(16) float xs[32][33];     // token-tile x k-chunk (scalar access only)
    __shared__ alignas(16) float ws[32][128];    // k-chunk x (k|v cols)   (float4 rows: 512B)
    __shared__ alignas(16) float ks[32][64];     // kphi tile              (float4 rows: 256B)
    __shared__ alignas(16) float vs[32][64];     // v tile

    const int bh    = blockIdx.x;          // 0..63
    const int chunk = blockIdx.y;          // 0..7
    const int tid   = threadIdx.x;
    const int b = bh >> 3, h = bh & 7;

    const float* xb = x + ((size_t)b*SEQ + chunk*512) * CDIM;

    // proj thread map: 2 tokens x 8 cols
    const int r2 = (tid >> 4) * 2;         // token pair base (0..30)
    const int cg = tid & 15;               // col group (cols cg*8..+8 of 128)
    // KV thread map: 4x4 fragment
    const int d0 = (tid & 15) * 4;
    const int e0 = (tid >> 4) * 4;

    float4 kv0 = {0,0,0,0}, kv1 = {0,0,0,0}, kv2 = {0,0,0,0}, kv3 = {0,0,0,0};
    float ksum = 0.0f;

    // global load maps
    const int xrow = tid >> 3, xc4 = (tid & 7) * 4;        // xs
    const int wr8  = tid >> 5, wc4 = (tid & 31) * 4;       // ws (4 rows apart by 8)

    for (int t = 0; t < 16; t++) {                 // 16 tiles of 32 tokens
        // ---- P1: projection GEMM over K=512 ----
        float4 o00 = {0,0,0,0}, o01 = {0,0,0,0}, o10 = {0,0,0,0}, o11 = {0,0,0,0};
        for (int kc = 0; kc < 16; kc++) {
            // stage x tile (32 tok x 32 k)
            {
                const float* src = xb + (size_t)(t*32 + xrow)*CDIM + kc*32 + xc4;
                xs[xrow][xc4+0] = src[0]; xs[xrow][xc4+1] = src[1];
                xs[xrow][xc4+2] = src[2]; xs[xrow][xc4+3] = src[3];
            }
            // stage W chunk (32 k x 128 cols : k-head | v-head)
            #pragma unroll
            for (int rr = 0; rr < 4; rr++) {
                const int wrow = wr8 + rr*8;
                const int cbase = wc4;                       // 0..124, stays inside one 64-col half
                const int gc = (cbase < 64) ? (512 + h*64 + cbase)
                                            : (1024 + h*64 + cbase - 64);
                const float* src = Wqkv + (size_t)(kc*32 + wrow)*1536 + gc;
                ws[wrow][cbase+0] = src[0]; ws[wrow][cbase+1] = src[1];
                ws[wrow][cbase+2] = src[2]; ws[wrow][cbase+3] = src[3];
            }
            __syncthreads();
            #pragma unroll
            for (int k = 0; k < 32; k++) {
                const float a0 = xs[r2][k], a1 = xs[r2+1][k];
                const float4 b0 = *(const float4*)&ws[k][cg*8];
                const float4 b1 = *(const float4*)&ws[k][cg*8+4];
                fma4(o00, a0, b0); fma4(o01, a0, b1);
                fma4(o10, a1, b0); fma4(o11, a1, b1);
            }
            __syncthreads();
        }
        // ---- P2: phi + scatter to ks/vs ----
        if (cg < 8) {
            float4 p;
            p.x=phi_map(o00.x); p.y=phi_map(o00.y); p.z=phi_map(o00.z); p.w=phi_map(o00.w);
            *(float4*)&ks[r2][cg*8] = p;
            p.x=phi_map(o01.x); p.y=phi_map(o01.y); p.z=phi_map(o01.z); p.w=phi_map(o01.w);
            *(float4*)&ks[r2][cg*8+4] = p;
            p.x=phi_map(o10.x); p.y=phi_map(o10.y); p.z=phi_map(o10.z); p.w=phi_map(o10.w);
            *(float4*)&ks[r2+1][cg*8] = p;
            p.x=phi_map(o11.x); p.y=phi_map(o11.y); p.z=phi_map(o11.z); p.w=phi_map(o11.w);
            *(float4*)&ks[r2+1][cg*8+4] = p;
        } else {
            const int e = cg*8 - 64;
            *(float4*)&vs[r2][e]     = o00;
            *(float4*)&vs[r2][e+4]   = o01;
            *(float4*)&vs[r2+1][e]   = o10;
            *(float4*)&vs[r2+1][e+4] = o11;
        }
        __syncthreads();
        // ---- P3: KV accumulation ----
        #pragma unroll
        for (int n = 0; n < 32; n++) {
            const float4 kk = *(const float4*)&ks[n][d0];
            const float4 vv = *(const float4*)&vs[n][e0];
            fma4(kv0, kk.x, vv); fma4(kv1, kk.y, vv);
            fma4(kv2, kk.z, vv); fma4(kv3, kk.w, vv);
            if (tid < 64) ksum += ks[n][tid];
        }
        __syncthreads();
    }

    float* dst = &g_KV_part[chunk][bh][0][0];
    *(float4*)&dst[(d0+0)*HD + e0] = kv0;
    *(float4*)&dst[(d0+1)*HD + e0] = kv1;
    *(float4*)&dst[(d0+2)*HD + e0] = kv2;
    *(float4*)&dst[(d0+3)*HD + e0] = kv3;
    if (tid < 64) g_Ksum_part[chunk][bh][tid] = ksum;
}

// ===========================================================================
// K2: reduce partials
// ===========================================================================
__global__ __launch_bounds__(256)
void kv_reduce_kernel()
{
    const int idx = blockIdx.x * 256 + threadIdx.x;
    if (idx < NBH*HD*HD) {
        const int bh = idx >> 12, r = idx & 4095;
        float s = 0.0f;
        #pragma unroll
        for (int p = 0; p < KVCH; p++) s += (&g_KV_part[p][bh][0][0])[r];
        (&g_KV[bh][0][0])[r] = s;
    }
    if (idx < NBH*HD) {
        const int bh = idx >> 6, d = idx & 63;
        float s = 0.0f;
        #pragma unroll
        for (int p = 0; p < KVCH; p++) s += g_Ksum_part[p][bh][d];
        g_Ksum[bh][d] = s;
    }
}

// ===========================================================================
// K3: fused q-projection + phi + attention matvec + normalize -> attn (fp16)
// Block = (token-block of 128, bh). 256 threads.
// wq padded to 68 floats/row: 272 B = 17*16 -> every float4 read aligned.
// ===========================================================================
struct alignas(16) K3P1 { float xs[128][33]; float wq[32][68]; };
struct alignas(16) K3P2 { __half qs[128][66]; float kvs[64][64]; float kss[64]; };

__global__ __launch_bounds__(256)
void q_attn_kernel(const float* __restrict__ x,
                   const float* __restrict__ Wqkv)
{
    __shared__ alignas(16) union K3U { K3P1 p1; K3P2 p2; } u;

    const int tb  = blockIdx.x;            // 0..31 token block
    const int bh  = blockIdx.y;            // 0..63
    const int tid = threadIdx.x;
    const int b = bh >> 3, h = bh & 7;
    const int tok0 = tb * 128;

    const float* xb = x + ((size_t)b*SEQ + tok0) * CDIM;

    const int r4 = (tid >> 3) * 4;         // 4 tokens (0..124)
    const int cg = tid & 7;                // 8 cols (d or e)

    // ---- P1: q projection (128 tok x 64 d), K=512 ----
    float4 q0[4], q1[4];
    #pragma unroll
    for (int i = 0; i < 4; i++) { q0[i] = make_float4(0,0,0,0); q1[i] = make_float4(0,0,0,0); }

    const int xr = tid >> 3, xc4 = (tid & 7) * 4;
    const int wr8 = tid >> 5, wc2 = (tid & 31) * 2;

    for (int kc = 0; kc < 16; kc++) {
        #pragma unroll
        for (int rr = 0; rr < 4; rr++) {
            const int row = xr + rr*32;
            const float* src = xb + (size_t)row*CDIM + kc*32 + xc4;
            u.p1.xs[row][xc4+0] = src[0]; u.p1.xs[row][xc4+1] = src[1];
            u.p1.xs[row][xc4+2] = src[2]; u.p1.xs[row][xc4+3] = src[3];
        }
        #pragma unroll
        for (int rr = 0; rr < 4; rr++) {
            const int wrow = wr8 + rr*8;
            const float* src = Wqkv + (size_t)(kc*32 + wrow)*1536 + h*64 + wc2;
            u.p1.wq[wrow][wc2+0] = src[0];
            u.p1.wq[wrow][wc2+1] = src[1];
        }
        __syncthreads();
        #pragma unroll
        for (int k = 0; k < 32; k++) {
            float a0 = u.p1.xs[r4+0][k], a1 = u.p1.xs[r4+1][k];
            float a2 = u.p1.xs[r4+2][k], a3 = u.p1.xs[r4+3][k];
            const float4 b0 = *(const float4*)&u.p1.wq[k][cg*8];
            const float4 b1 = *(const float4*)&u.p1.wq[k][cg*8+4];
            fma4(q0[0], a0, b0); fma4(q1[0], a0, b1);
            fma4(q0[1], a1, b0); fma4(q1[1], a1, b1);
            fma4(q0[2], a2, b0); fma4(q1[2], a2, b1);
            fma4(q0[3], a3, b0); fma4(q1[3], a3, b1);
        }
        __syncthreads();
    }

    // ---- P2: phi -> qs (half); load KV + Ksum into smem ----
    #pragma unroll
    for (int i = 0; i < 4; i++) {
        u.p2.qs[r4+i][cg*8+0] = __float2half(phi_map(q0[i].x));
        u.p2.qs[r4+i][cg*8+1] = __float2half(phi_map(q0[i].y));
        u.p2.qs[r4+i][cg*8+2] = __float2half(phi_map(q0[i].z));
        u.p2.qs[r4+i][cg*8+3] = __float2half(phi_map(q0[i].w));
        u.p2.qs[r4+i][cg*8+4] = __float2half(phi_map(q1[i].x));
        u.p2.qs[r4+i][cg*8+5] = __float2half(phi_map(q1[i].y));
        u.p2.qs[r4+i][cg*8+6] = __float2half(phi_map(q1[i].z));
        u.p2.qs[r4+i][cg*8+7] = __float2half(phi_map(q1[i].w));
    }
    {
        const int row = tid >> 2, c16 = (tid & 3) * 16;
        const float* src = &g_KV[bh][row][c16];
        #pragma unroll
        for (int j = 0; j < 16; j++) u.p2.kvs[row][c16+j] = src[j];
        if (tid < 64) u.p2.kss[tid] = g_Ksum[bh][tid];
    }
    __syncthreads();

    // ---- P3: out = qphi @ KV ; denom = qphi . Ksum ----
    float4 oa0[4], oa1[4];
    float den[4];
    #pragma unroll
    for (int i = 0; i < 4; i++) { oa0[i] = make_float4(0,0,0,0); oa1[i] = make_float4(0,0,0,0); den[i] = 0.0f; }

    #pragma unroll 8
    for (int d = 0; d < 64; d++) {
        const float4 b0 = *(const float4*)&u.p2.kvs[d][cg*8];
        const float4 b1 = *(const float4*)&u.p2.kvs[d][cg*8+4];
        const float kd = u.p2.kss[d];
        #pragma unroll
        for (int i = 0; i < 4; i++) {
            const float qd = __half2float(u.p2.qs[r4+i][d]);
            fma4(oa0[i], qd, b0);
            fma4(oa1[i], qd, b1);
            den[i] += qd * kd;
        }
    }

    // ---- P4: normalize + store fp16 attn ----
    #pragma unroll
    for (int i = 0; i < 4; i++) {
        const float inv = 1.0f / (den[i] + 1e-6f);
        const int n = tok0 + r4 + i;
        const size_t base = ((size_t)(b*SEQ + n))*CDIM + h*64 + cg*8;
        __half2* dst = (__half2*)&g_attnh[base];
        dst[0] = __floats2half2_rn(oa0[i].x*inv, oa0[i].y*inv);
        dst[1] = __floats2half2_rn(oa0[i].z*inv, oa0[i].w*inv);
        dst[2] = __floats2half2_rn(oa1[i].x*inv, oa1[i].y*inv);
        dst[3] = __floats2half2_rn(oa1[i].z*inv, oa1[i].w*inv);
    }
}

// ===========================================================================
// K4: out projection: out = attn(fp16) @ W_out + bias   (fp32 out)
// 128x128 tile, BK=8, 256 threads, 8x8 per thread.
// ===========================================================================
__global__ __launch_bounds__(256)
void out_proj_kernel(const float* __restrict__ Wout,
                     const float* __restrict__ bias,
                     float* __restrict__ Cout)
{
    __shared__ alignas(16) float As[8][128];   // As[k][m]
    __shared__ alignas(16) float Bs[8][128];   // Bs[k][n]

    const int tid  = threadIdx.x;
    const int brow = blockIdx.x;
    const int bcol = blockIdx.y;
    const int tx = tid & 15;
    const int ty = tid >> 4;

    const int arow = tid >> 1;
    const int acol = (tid & 1) * 4;
    const int bkr  = tid >> 5;
    const int bc4  = (tid & 31) * 4;

    const __half* Ap = g_attnh + (size_t)(brow*128 + arow)*CDIM + acol;
    const float*  Bp = Wout + (size_t)bkr*CDIM + bcol*128 + bc4;

    float4 acc0[8], acc1[8];
    #pragma unroll
    for (int i = 0; i < 8; i++) { acc0[i] = make_float4(0,0,0,0); acc1[i] = make_float4(0,0,0,0); }

    for (int kt = 0; kt < 64; kt++) {
        As[acol+0][arow] = __half2float(Ap[kt*8+0]);
        As[acol+1][arow] = __half2float(Ap[kt*8+1]);
        As[acol+2][arow] = __half2float(Ap[kt*8+2]);
        As[acol+3][arow] = __half2float(Ap[kt*8+3]);
        const float* bsrc = Bp + (size_t)kt*8*CDIM;
        Bs[bkr][bc4+0] = bsrc[0]; Bs[bkr][bc4+1] = bsrc[1];
        Bs[bkr][bc4+2] = bsrc[2]; Bs[bkr][bc4+3] = bsrc[3];
        __syncthreads();
        #pragma unroll
        for (int k = 0; k < 8; k++) {
            const float4 fa0 = *(const float4*)&As[k][ty*8];
            const float4 fa1 = *(const float4*)&As[k][ty*8+4];
            const float4 fb0 = *(const float4*)&Bs[k][tx*8];
            const float4 fb1 = *(const float4*)&Bs[k][tx*8+4];
            #pragma unroll
            for (int i = 0; i < 4; i++) {
                const float a = f4c(fa0, i);
                fma4(acc0[i], a, fb0); fma4(acc1[i], a, fb1);
            }
            #pragma unroll
            for (int i = 0; i < 4; i++) {
                const float a = f4c(fa1, i);
                fma4(acc0[4+i], a, fb0); fma4(acc1[4+i], a, fb1);
            }
        }
        __syncthreads();
    }

    const int r0 = brow*128 + ty*8;
    const int c0 = bcol*128 + tx*8;
    const float4 bi0 = *(const float4*)&bias[c0];
    const float4 bi1 = *(const float4*)&bias[c0+4];
    #pragma unroll
    for (int i = 0; i < 8; i++) {
        float* o = Cout + (size_t)(r0+i)*CDIM + c0;
        o[0] = acc0[i].x + bi0.x; o[1] = acc0[i].y + bi0.y;
        o[2] = acc0[i].z + bi0.z; o[3] = acc0[i].w + bi0.w;
        o[4] = acc1[i].x + bi1.x; o[5] = acc1[i].y + bi1.y;
        o[6] = acc1[i].z + bi1.z; o[7] = acc1[i].w + bi1.w;
    }
}

// ===========================================================================
extern "C" void kernel_launch(void* const* d_in, const int* in_sizes, int n_in,
                              void* d_out, int out_size)
{
    const float* x     = (const float*)d_in[0];   // [8,4096,512]
    const float* W_qkv = (const float*)d_in[1];   // [512,1536]
    const float* W_out = (const float*)d_in[2];   // [512,512]
    const float* b_out = (const float*)d_in[3];   // [512]
    float* out = (float*)d_out;                   // [8,4096,512]

    {   // K1: fused k,v projection + KV/Ksum partials
        dim3 grid(NBH, KVCH);                // 64 x 8
        kv_build_kernel<<<grid, 256>>>(x, W_qkv);
    }
    // K2: reduce partials
    kv_reduce_kernel<<<(NBH*HD*HD + 255)/256, 256>>>();
    {   // K3: fused q projection + attention + normalize
        dim3 grid(SEQ/128, NBH);             // 32 x 64
        q_attn_kernel<<<grid, 256>>>(x, W_qkv);
    }
    {   // K4: output projection + bias
        dim3 grid(MROWS/128, CDIM/128);      // 256 x 4
        out_proj_kernel<<<grid, 256>>>(W_out, b_out, out);
    }
}

// round 7
// speedup vs baseline: 5.4329x; 5.4329x over previous
#include <cuda_runtime.h>
#include <cuda_fp16.h>
#include <cstdint>
#include <math.h>

#define BB   8
#define SEQ  4096
#define CDIM 512
#define NH   8
#define HD   64
#define MROWS (BB*SEQ)   // 32768
#define NBH  (BB*NH)     // 64
#define KVCH 8

// ---------------- static device scratch (~42 MB, known-safe) --------------
__device__ float  g_KV_part[KVCH][NBH][HD][HD];
__device__ float  g_Ksum_part[KVCH][NBH][HD];
__device__ float  g_KV[NBH][HD][HD];
__device__ float  g_Ksum[NBH][HD];
__device__ __half g_attnh[(size_t)MROWS*CDIM];    // 32 MB

__device__ __forceinline__ float phi_map(float x) {
    return x > 0.0f ? x + 1.0f : __expf(x);
}

// ---- mma.sync m16n8k16 fp16 -> fp32 --------------------------------------
__device__ __forceinline__ void mma16816(float* c,
    uint32_t a0, uint32_t a1, uint32_t a2, uint32_t a3,
    uint32_t b0, uint32_t b1)
{
    asm volatile(
        "mma.sync.aligned.m16n8k16.row.col.f32.f16.f16.f32 "
        "{%0,%1,%2,%3},{%4,%5,%6,%7},{%8,%9},{%0,%1,%2,%3};"
        : "+f"(c[0]), "+f"(c[1]), "+f"(c[2]), "+f"(c[3])
        : "r"(a0), "r"(a1), "r"(a2), "r"(a3), "r"(b0), "r"(b1));
}

// A 16x16 row-major fragment from k-contiguous smem tile (base at (row0,k0))
__device__ __forceinline__ void ldAfrag(const __half* p, int stride, int g, int tig, uint32_t* a) {
    a[0] = *(const uint32_t*)(p + (size_t)g*stride     + tig*2);
    a[1] = *(const uint32_t*)(p + (size_t)(g+8)*stride + tig*2);
    a[2] = *(const uint32_t*)(p + (size_t)g*stride     + tig*2 + 8);
    a[3] = *(const uint32_t*)(p + (size_t)(g+8)*stride + tig*2 + 8);
}
// B 16x8 col fragment from [n][k] (k-contiguous) smem tile (base at (n0,k0))
__device__ __forceinline__ void ldBfrag(const __half* p, int stride, int g, int tig, uint32_t* bf) {
    bf[0] = *(const uint32_t*)(p + (size_t)g*stride + tig*2);
    bf[1] = *(const uint32_t*)(p + (size_t)g*stride + tig*2 + 8);
}

// ===========================================================================
// K1: fused k/v projection (mma) + KV/Ksum accumulation (mma).
// Block = (bh, chunk of 512 tokens), 256 threads (8 warps).
// ===========================================================================
#define SX1 40    // Xs/Wt row stride (halves)
#define SKT 136   // kT/vT row stride (halves)

struct K1A { __half Xs[128][SX1]; __half Wt[128][SX1]; };   // 20480 B
struct K1B { __half kT[64][SKT];  __half vT[64][SKT];  };   // 34816 B

__global__ __launch_bounds__(256, 1)
void kv_build_kernel(const float* __restrict__ x, const float* __restrict__ Wqkv)
{
    __shared__ union { K1A a; K1B b; } u;

    const int bh = blockIdx.x, chunk = blockIdx.y;
    const int tid = threadIdx.x, lane = tid & 31, warp = tid >> 5;
    const int g = lane >> 2, tig = lane & 3;
    const int b = bh >> 3, h = bh & 7;

    // proj warp grid 4x2 (warp tile 32x64 over 128x128)
    const int pm0 = (warp >> 1) * 32;
    const int pni = warp & 1;
    const int pn0 = pni * 64;
    // KV warp grid 2x4 (warp tile 32x16 over 64x64)
    const int kd0 = (warp >> 2) * 32;
    const int ke0 = (warp & 3) * 16;

    float kvacc[2][2][4] = {};
    float ksum = 0.0f;

    const float* xb = x + ((size_t)b*SEQ + chunk*512) * CDIM;
    const int srow = tid >> 1, sside = (tid & 1) * 16;

    for (int st = 0; st < 4; st++) {                // 4 x 128-token subtiles
        float cacc[2][8][4] = {};
        for (int kc = 0; kc < 16; kc++) {           // K=512 in 32-chunks
            {   // stage X (fp32 -> fp16)
                const float* src = xb + (size_t)(st*128 + srow)*CDIM + kc*32 + sside;
                #pragma unroll
                for (int j = 0; j < 16; j += 4) {
                    const float4 vx = *(const float4*)(src + j);
                    u.a.Xs[srow][sside+j+0] = __float2half(vx.x);
                    u.a.Xs[srow][sside+j+1] = __float2half(vx.y);
                    u.a.Xs[srow][sside+j+2] = __float2half(vx.z);
                    u.a.Xs[srow][sside+j+3] = __float2half(vx.w);
                }
            }
            {   // stage W transposed: Wt[n][k] ; n<64 = k-head cols, n>=64 = v-head
                const int n = srow;
                const int gcol = (n < 64) ? (512 + h*64 + n) : (1024 + h*64 + (n - 64));
                const float* src = Wqkv + (size_t)(kc*32 + sside)*1536 + gcol;
                #pragma unroll
                for (int j = 0; j < 16; j++)
                    u.a.Wt[n][sside+j] = __float2half(src[(size_t)j*1536]);
            }
            __syncthreads();
            #pragma unroll
            for (int kh = 0; kh < 2; kh++) {
                uint32_t af[2][4], bf[8][2];
                #pragma unroll
                for (int mt = 0; mt < 2; mt++)
                    ldAfrag(&u.a.Xs[pm0 + mt*16][kh*16], SX1, g, tig, af[mt]);
                #pragma unroll
                for (int nt = 0; nt < 8; nt++)
                    ldBfrag(&u.a.Wt[pn0 + nt*8][kh*16], SX1, g, tig, bf[nt]);
                #pragma unroll
                for (int mt = 0; mt < 2; mt++)
                    #pragma unroll
                    for (int nt = 0; nt < 8; nt++)
                        mma16816(cacc[mt][nt], af[mt][0],af[mt][1],af[mt][2],af[mt][3],
                                 bf[nt][0], bf[nt][1]);
            }
            __syncthreads();
        }
        // epilogue: phi + transposed fp16 store (union flips A->B; last sync covers it)
        #pragma unroll
        for (int mt = 0; mt < 2; mt++) {
            const int r0 = pm0 + mt*16 + g;
            #pragma unroll
            for (int nt = 0; nt < 8; nt++) {
                const int c = pn0 + nt*8 + tig*2;
                const float* cc = cacc[mt][nt];
                if (pni == 0) {
                    u.b.kT[c+0][r0]   = __float2half(phi_map(cc[0]));
                    u.b.kT[c+1][r0]   = __float2half(phi_map(cc[1]));
                    u.b.kT[c+0][r0+8] = __float2half(phi_map(cc[2]));
                    u.b.kT[c+1][r0+8] = __float2half(phi_map(cc[3]));
                } else {
                    const int e = c - 64;
                    u.b.vT[e+0][r0]   = __float2half(cc[0]);
                    u.b.vT[e+1][r0]   = __float2half(cc[1]);
                    u.b.vT[e+0][r0+8] = __float2half(cc[2]);
                    u.b.vT[e+1][r0+8] = __float2half(cc[3]);
                }
            }
        }
        __syncthreads();
        // Ksum over this subtile (reads kT fp16 -> consistent with KV mma inputs)
        if (tid < 64) {
            #pragma unroll 8
            for (int n = 0; n < 128; n++) ksum += __half2float(u.b.kT[tid][n]);
        }
        // KV += kT[64 x 128] @ vT^T : A=kT row-major, B=vT as col fragments
        #pragma unroll
        for (int ks = 0; ks < 8; ks++) {
            uint32_t af[2][4], bf[2][2];
            #pragma unroll
            for (int mt = 0; mt < 2; mt++)
                ldAfrag(&u.b.kT[kd0 + mt*16][ks*16], SKT, g, tig, af[mt]);
            #pragma unroll
            for (int nt = 0; nt < 2; nt++)
                ldBfrag(&u.b.vT[ke0 + nt*8][ks*16], SKT, g, tig, bf[nt]);
            #pragma unroll
            for (int mt = 0; mt < 2; mt++)
                #pragma unroll
                for (int nt = 0; nt < 2; nt++)
                    mma16816(kvacc[mt][nt], af[mt][0],af[mt][1],af[mt][2],af[mt][3],
                             bf[nt][0], bf[nt][1]);
        }
        __syncthreads();
    }
    // write partials
    #pragma unroll
    for (int mt = 0; mt < 2; mt++) {
        const int d = kd0 + mt*16 + g;
        #pragma unroll
        for (int nt = 0; nt < 2; nt++) {
            const int e = ke0 + nt*8 + tig*2;
            g_KV_part[chunk][bh][d  ][e  ] = kvacc[mt][nt][0];
            g_KV_part[chunk][bh][d  ][e+1] = kvacc[mt][nt][1];
            g_KV_part[chunk][bh][d+8][e  ] = kvacc[mt][nt][2];
            g_KV_part[chunk][bh][d+8][e+1] = kvacc[mt][nt][3];
        }
    }
    if (tid < 64) g_Ksum_part[chunk][bh][tid] = ksum;
}

// ===========================================================================
// K2: reduce partials
// ===========================================================================
__global__ __launch_bounds__(256)
void kv_reduce_kernel()
{
    const int idx = blockIdx.x * 256 + threadIdx.x;
    if (idx < NBH*HD*HD) {
        const int bh = idx >> 12, r = idx & 4095;
        float s = 0.0f;
        #pragma unroll
        for (int p = 0; p < KVCH; p++) s += (&g_KV_part[p][bh][0][0])[r];
        (&g_KV[bh][0][0])[r] = s;
    }
    if (idx < NBH*HD) {
        const int bh = idx >> 6, d = idx & 63;
        float s = 0.0f;
        #pragma unroll
        for (int p = 0; p < KVCH; p++) s += g_Ksum_part[p][bh][d];
        g_Ksum[bh][d] = s;
    }
}

// ===========================================================================
// K3: fused q projection (mma) + phi + attn matvec (mma) + normalize.
// Block = (128-token block, bh), 256 threads.
// ===========================================================================
#define SX3 40
#define SQ3 72

struct K3A { __half Xs[128][SX3]; __half Wt[64][SX3]; };                         // 15360 B
struct K3B { __half qs[128][SQ3]; __half KVt[64][SQ3]; float kss[64]; float den[128]; }; // 28416 B

__global__ __launch_bounds__(256, 1)
void q_attn_kernel(const float* __restrict__ x, const float* __restrict__ Wqkv)
{
    __shared__ union { K3A a; K3B b; } u;

    const int tb = blockIdx.x, bh = blockIdx.y;
    const int tid = threadIdx.x, lane = tid & 31, warp = tid >> 5;
    const int g = lane >> 2, tig = lane & 3;
    const int b = bh >> 3, h = bh & 7;
    const int tok0 = tb * 128;

    const int m0 = (warp >> 1) * 32;   // warp grid 4x2, warp tile 32x32
    const int n0 = (warp & 1) * 32;

    const float* xb = x + ((size_t)b*SEQ + tok0) * CDIM;
    const int srow = tid >> 1, sside = (tid & 1) * 16;

    // ---- q projection: 128 x 64, K = 512 ----
    float cacc[2][4][4] = {};
    for (int kc = 0; kc < 16; kc++) {
        {
            const float* src = xb + (size_t)srow*CDIM + kc*32 + sside;
            #pragma unroll
            for (int j = 0; j < 16; j += 4) {
                const float4 vx = *(const float4*)(src + j);
                u.a.Xs[srow][sside+j+0] = __float2half(vx.x);
                u.a.Xs[srow][sside+j+1] = __float2half(vx.y);
                u.a.Xs[srow][sside+j+2] = __float2half(vx.z);
                u.a.Xs[srow][sside+j+3] = __float2half(vx.w);
            }
        }
        if (tid < 128) {
            const int n = tid >> 1, ss = (tid & 1) * 16;
            const float* src = Wqkv + (size_t)(kc*32 + ss)*1536 + h*64 + n;
            #pragma unroll
            for (int j = 0; j < 16; j++)
                u.a.Wt[n][ss+j] = __float2half(src[(size_t)j*1536]);
        }
        __syncthreads();
        #pragma unroll
        for (int kh = 0; kh < 2; kh++) {
            uint32_t af[2][4], bf[4][2];
            #pragma unroll
            for (int mt = 0; mt < 2; mt++)
                ldAfrag(&u.a.Xs[m0 + mt*16][kh*16], SX3, g, tig, af[mt]);
            #pragma unroll
            for (int nt = 0; nt < 4; nt++)
                ldBfrag(&u.a.Wt[n0 + nt*8][kh*16], SX3, g, tig, bf[nt]);
            #pragma unroll
            for (int mt = 0; mt < 2; mt++)
                #pragma unroll
                for (int nt = 0; nt < 4; nt++)
                    mma16816(cacc[mt][nt], af[mt][0],af[mt][1],af[mt][2],af[mt][3],
                             bf[nt][0], bf[nt][1]);
        }
        __syncthreads();
    }
    // ---- epilogue: qs = phi(q) fp16 ; load KV (transposed) + Ksum ----
    #pragma unroll
    for (int mt = 0; mt < 2; mt++) {
        const int r0 = m0 + mt*16 + g;
        #pragma unroll
        for (int nt = 0; nt < 4; nt++) {
            const int c = n0 + nt*8 + tig*2;
            const float* cc = cacc[mt][nt];
            u.b.qs[r0  ][c  ] = __float2half(phi_map(cc[0]));
            u.b.qs[r0  ][c+1] = __float2half(phi_map(cc[1]));
            u.b.qs[r0+8][c  ] = __float2half(phi_map(cc[2]));
            u.b.qs[r0+8][c+1] = __float2half(phi_map(cc[3]));
        }
    }
    {
        #pragma unroll
        for (int i = 0; i < 16; i++) {
            const int lin = tid*16 + i;
            const int d = lin >> 6, e = lin & 63;
            u.b.KVt[e][d] = __float2half(g_KV[bh][d][e]);
        }
        if (tid < 64) u.b.kss[tid] = g_Ksum[bh][tid];
    }
    __syncthreads();
    if (tid < 128) {
        float s = 0.0f;
        #pragma unroll
        for (int d = 0; d < 64; d++) s += __half2float(u.b.qs[tid][d]) * u.b.kss[d];
        u.b.den[tid] = s;
    }
    __syncthreads();
    // ---- attn = qphi @ KV  (K = 64) ----
    float oacc[2][4][4] = {};
    #pragma unroll
    for (int ks = 0; ks < 4; ks++) {
        uint32_t af[2][4], bf[4][2];
        #pragma unroll
        for (int mt = 0; mt < 2; mt++)
            ldAfrag(&u.b.qs[m0 + mt*16][ks*16], SQ3, g, tig, af[mt]);
        #pragma unroll
        for (int nt = 0; nt < 4; nt++)
            ldBfrag(&u.b.KVt[n0 + nt*8][ks*16], SQ3, g, tig, bf[nt]);
        #pragma unroll
        for (int mt = 0; mt < 2; mt++)
            #pragma unroll
            for (int nt = 0; nt < 4; nt++)
                mma16816(oacc[mt][nt], af[mt][0],af[mt][1],af[mt][2],af[mt][3],
                         bf[nt][0], bf[nt][1]);
    }
    // ---- normalize + fp16 store ----
    #pragma unroll
    for (int mt = 0; mt < 2; mt++) {
        const int r0 = m0 + mt*16 + g;
        const float inv0 = 1.0f / (u.b.den[r0]   + 1e-6f);
        const float inv1 = 1.0f / (u.b.den[r0+8] + 1e-6f);
        #pragma unroll
        for (int nt = 0; nt < 4; nt++) {
            const int c = n0 + nt*8 + tig*2;
            const float* cc = oacc[mt][nt];
            __half2* d0p = (__half2*)&g_attnh[((size_t)(b*SEQ + tok0 + r0  ))*CDIM + h*64 + c];
            __half2* d1p = (__half2*)&g_attnh[((size_t)(b*SEQ + tok0 + r0+8))*CDIM + h*64 + c];
            *d0p = __floats2half2_rn(cc[0]*inv0, cc[1]*inv0);
            *d1p = __floats2half2_rn(cc[2]*inv1, cc[3]*inv1);
        }
    }
}

// ===========================================================================
// K4: out = attnh(fp16) @ W_out + bias  (mma), 128x128 tile.
// ===========================================================================
#define SX4 40

__global__ __launch_bounds__(256, 1)
void out_proj_kernel(const float* __restrict__ Wout,
                     const float* __restrict__ bias,
                     float* __restrict__ Cout)
{
    __shared__ __half Xs[128][SX4];
    __shared__ __half Wt[128][SX4];

    const int tid = threadIdx.x, lane = tid & 31, warp = tid >> 5;
    const int g = lane >> 2, tig = lane & 3;
    const int brow = blockIdx.x, bcol = blockIdx.y;
    const int m0 = (warp >> 1) * 32;
    const int n0w = (warp & 1) * 64;
    const int srow = tid >> 1, sside = (tid & 1) * 16;

    float cacc[2][8][4] = {};
    for (int kc = 0; kc < 16; kc++) {
        {   // A: already fp16
            const __half* src = g_attnh + (size_t)(brow*128 + srow)*CDIM + kc*32 + sside;
            *(uint4*)&Xs[srow][sside]     = *(const uint4*)(src);
            *(uint4*)&Xs[srow][sside + 8] = *(const uint4*)(src + 8);
        }
        {   // B transposed: Wt[n][k]
            const int n = srow;
            const float* src = Wout + (size_t)(kc*32 + sside)*CDIM + bcol*128 + n;
            #pragma unroll
            for (int j = 0; j < 16; j++)
                Wt[n][sside+j] = __float2half(src[(size_t)j*CDIM]);
        }
        __syncthreads();
        #pragma unroll
        for (int kh = 0; kh < 2; kh++) {
            uint32_t af[2][4], bf[8][2];
            #pragma unroll
            for (int mt = 0; mt < 2; mt++)
                ldAfrag(&Xs[m0 + mt*16][kh*16], SX4, g, tig, af[mt]);
            #pragma unroll
            for (int nt = 0; nt < 8; nt++)
                ldBfrag(&Wt[n0w + nt*8][kh*16], SX4, g, tig, bf[nt]);
            #pragma unroll
            for (int mt = 0; mt < 2; mt++)
                #pragma unroll
                for (int nt = 0; nt < 8; nt++)
                    mma16816(cacc[mt][nt], af[mt][0],af[mt][1],af[mt][2],af[mt][3],
                             bf[nt][0], bf[nt][1]);
        }
        __syncthreads();
    }
    #pragma unroll
    for (int mt = 0; mt < 2; mt++) {
        const int r0 = brow*128 + m0 + mt*16 + g;
        #pragma unroll
        for (int nt = 0; nt < 8; nt++) {
            const int c = bcol*128 + n0w + nt*8 + tig*2;
            const float2 bv = *(const float2*)&bias[c];
            const float* cc = cacc[mt][nt];
            float2 o0 = { cc[0] + bv.x, cc[1] + bv.y };
            float2 o1 = { cc[2] + bv.x, cc[3] + bv.y };
            *(float2*)&Cout[(size_t)r0*CDIM + c]     = o0;
            *(float2*)&Cout[(size_t)(r0+8)*CDIM + c] = o1;
        }
    }
}

// ===========================================================================
extern "C" void kernel_launch(void* const* d_in, const int* in_sizes, int n_in,
                              void* d_out, int out_size)
{
    const float* x     = (const float*)d_in[0];
    const float* W_qkv = (const float*)d_in[1];
    const float* W_out = (const float*)d_in[2];
    const float* b_out = (const float*)d_in[3];
    float* out = (float*)d_out;

    {   dim3 grid(NBH, KVCH);                 // 64 x 8
        kv_build_kernel<<<grid, 256>>>(x, W_qkv); }
    kv_reduce_kernel<<<(NBH*HD*HD + 255)/256, 256>>>();
    {   dim3 grid(SEQ/128, NBH);              // 32 x 64
        q_attn_kernel<<<grid, 256>>>(x, W_qkv); }
    {   dim3 grid(MROWS/128, CDIM/128);       // 256 x 4
        out_proj_kernel<<<grid, 256>>>(W_out, b_out, out); }
}

// round 8
// speedup vs baseline: 6.1394x; 1.1300x over previous
#include <cuda_runtime.h>
#include <cuda_fp16.h>
#include <cstdint>
#include <math.h>

#define BB   8
#define SEQ  4096
#define CDIM 512
#define NH   8
#define HD   64
#define MROWS (BB*SEQ)   // 32768
#define NBH  (BB*NH)     // 64
#define KVCH 8

// ---------------- static device scratch (~44 MB) ---------------------------
__device__ float  g_KV_part[KVCH][NBH][HD][HD];
__device__ float  g_Ksum_part[KVCH][NBH][HD];
__device__ float  g_KV[NBH][HD][HD];
__device__ float  g_Ksum[NBH][HD];
__device__ __half g_attnh[(size_t)MROWS*CDIM];    // 32 MB
__device__ __half g_WqkvT[3*CDIM][CDIM];          // 1.5 MB  [out_col][k]
__device__ __half g_WoutT[CDIM][CDIM];            // 0.5 MB  [out_col][k]

__device__ __forceinline__ float phi_map(float x) {
    return x > 0.0f ? x + 1.0f : __expf(x);
}
__device__ __forceinline__ uint32_t f2h2(float a, float b) {
    __half2 h = __floats2half2_rn(a, b);
    return *reinterpret_cast<uint32_t*>(&h);
}

// ---- mma.sync m16n8k16 fp16 -> fp32 --------------------------------------
__device__ __forceinline__ void mma16816(float* c,
    uint32_t a0, uint32_t a1, uint32_t a2, uint32_t a3,
    uint32_t b0, uint32_t b1)
{
    asm volatile(
        "mma.sync.aligned.m16n8k16.row.col.f32.f16.f16.f32 "
        "{%0,%1,%2,%3},{%4,%5,%6,%7},{%8,%9},{%0,%1,%2,%3};"
        : "+f"(c[0]), "+f"(c[1]), "+f"(c[2]), "+f"(c[3])
        : "r"(a0), "r"(a1), "r"(a2), "r"(a3), "r"(b0), "r"(b1));
}

// ldmatrix x4 of a 16x16 fp16 tile at (row0, k0), row stride S halves.
// For A (rows = m): r = {a0,a1,a2,a3} of m16n8k16.
// For B (rows = n, 16 n-rows): r = {b0(n0..7), b0(n8..15), b1(n0..7), b1(n8..15)}.
__device__ __forceinline__ void ldsm16x16(const __half* tile, int S, int lane, uint32_t* r) {
    const int t = lane >> 3, j = lane & 7;
    const __half* addr = tile + (size_t)(((t & 1) << 3) + j) * S + ((t >> 1) << 3);
    uint32_t a = (uint32_t)__cvta_generic_to_shared(addr);
    asm volatile("ldmatrix.sync.aligned.m8n8.x4.shared.b16 {%0,%1,%2,%3}, [%4];"
                 : "=r"(r[0]), "=r"(r[1]), "=r"(r[2]), "=r"(r[3]) : "r"(a));
}

// ===========================================================================
// K0: W[R][C] fp32  ->  WT[C][R] fp16   (32x32 smem tile transpose)
// ===========================================================================
__global__ __launch_bounds__(256)
void transpose_w_kernel(const float* __restrict__ W, __half* __restrict__ WT,
                        int R, int C)
{
    __shared__ __half ts[32][33];
    const int tid = threadIdx.x;
    const int r = tid >> 3, c4 = (tid & 7) * 4;
    const float* src = W + (size_t)(blockIdx.y*32 + r)*C + blockIdx.x*32 + c4;
    const float4 v = *(const float4*)src;
    ts[c4+0][r] = __float2half(v.x);
    ts[c4+1][r] = __float2half(v.y);
    ts[c4+2][r] = __float2half(v.z);
    ts[c4+3][r] = __float2half(v.w);
    __syncthreads();
    __half* dst = WT + (size_t)(blockIdx.x*32 + r)*R + blockIdx.y*32 + c4;
    dst[0] = ts[r][c4+0]; dst[1] = ts[r][c4+1];
    dst[2] = ts[r][c4+2]; dst[3] = ts[r][c4+3];
}

// ===========================================================================
// K1: fused k/v projection (mma) + KV/Ksum accumulation (mma).
// Block = (bh, chunk of 512 tokens), 256 threads (8 warps).
// ===========================================================================
#define SX1 40    // Xs/Wt row stride (halves): 80B, 16B-aligned rows
#define SKT 136   // kT/vT row stride (halves): 272B

struct K1A { __half Xs[128][SX1]; __half Wt[128][SX1]; };   // 20480 B
struct K1B { __half kT[64][SKT];  __half vT[64][SKT];  };   // 34816 B

__global__ __launch_bounds__(256, 1)
void kv_build_kernel(const float* __restrict__ x)
{
    __shared__ alignas(16) union { K1A a; K1B b; } u;
    __shared__ float red[256];

    const int bh = blockIdx.x, chunk = blockIdx.y;
    const int tid = threadIdx.x, lane = tid & 31, warp = tid >> 5;
    const int g = lane >> 2, tig = lane & 3;
    const int b = bh >> 3, h = bh & 7;

    const int pm0 = (warp >> 1) * 32;      // proj warp grid 4x2
    const int pni = warp & 1;
    const int pn0 = pni * 64;
    const int kd0 = (warp >> 2) * 32;      // KV warp grid 2x4
    const int ke0 = (warp & 3) * 16;

    float kvacc[2][2][4] = {};
    float ksum = 0.0f;

    const float* xb = x + ((size_t)b*SEQ + chunk*512) * CDIM;
    const int srow = tid >> 1, sside = (tid & 1) * 16;
    // Wt global rows for this thread's staging row
    const int wgn = (srow < 64) ? (512 + h*64 + srow) : (1024 + h*64 + (srow - 64));

    for (int st = 0; st < 4; st++) {                // 4 x 128-token subtiles
        float cacc[2][8][4] = {};
        for (int kc = 0; kc < 16; kc++) {           // K=512 in 32-chunks
            {   // stage X (fp32 -> fp16), 16 halves/thread, 2x 16B stores
                const float* src = xb + (size_t)(st*128 + srow)*CDIM + kc*32 + sside;
                const float4 v0 = *(const float4*)(src);
                const float4 v1 = *(const float4*)(src + 4);
                const float4 v2 = *(const float4*)(src + 8);
                const float4 v3 = *(const float4*)(src + 12);
                uint4 w0, w1;
                w0.x = f2h2(v0.x, v0.y); w0.y = f2h2(v0.z, v0.w);
                w0.z = f2h2(v1.x, v1.y); w0.w = f2h2(v1.z, v1.w);
                w1.x = f2h2(v2.x, v2.y); w1.y = f2h2(v2.z, v2.w);
                w1.z = f2h2(v3.x, v3.y); w1.w = f2h2(v3.z, v3.w);
                *(uint4*)&u.a.Xs[srow][sside]     = w0;
                *(uint4*)&u.a.Xs[srow][sside + 8] = w1;
            }
            {   // stage W from pre-transposed fp16 (coalesced uint4)
                const __half* src = &g_WqkvT[wgn][kc*32 + sside];
                *(uint4*)&u.a.Wt[srow][sside]     = *(const uint4*)(src);
                *(uint4*)&u.a.Wt[srow][sside + 8] = *(const uint4*)(src + 8);
            }
            __syncthreads();
            #pragma unroll
            for (int kh = 0; kh < 2; kh++) {
                uint32_t af[2][4], bq[4][4];
                #pragma unroll
                for (int mt = 0; mt < 2; mt++)
                    ldsm16x16(&u.a.Xs[pm0 + mt*16][kh*16], SX1, lane, af[mt]);
                #pragma unroll
                for (int np = 0; np < 4; np++)
                    ldsm16x16(&u.a.Wt[pn0 + np*16][kh*16], SX1, lane, bq[np]);
                #pragma unroll
                for (int mt = 0; mt < 2; mt++)
                    #pragma unroll
                    for (int nt = 0; nt < 8; nt++)
                        mma16816(cacc[mt][nt],
                                 af[mt][0], af[mt][1], af[mt][2], af[mt][3],
                                 bq[nt>>1][nt&1], bq[nt>>1][2 + (nt&1)]);
            }
            __syncthreads();
        }
        // epilogue: phi + transposed fp16 store into kT/vT
        #pragma unroll
        for (int mt = 0; mt < 2; mt++) {
            const int r0 = pm0 + mt*16 + g;
            #pragma unroll
            for (int nt = 0; nt < 8; nt++) {
                const int c = pn0 + nt*8 + tig*2;
                const float* cc = cacc[mt][nt];
                if (pni == 0) {
                    u.b.kT[c+0][r0]   = __float2half(phi_map(cc[0]));
                    u.b.kT[c+1][r0]   = __float2half(phi_map(cc[1]));
                    u.b.kT[c+0][r0+8] = __float2half(phi_map(cc[2]));
                    u.b.kT[c+1][r0+8] = __float2half(phi_map(cc[3]));
                } else {
                    const int e = c - 64;
                    u.b.vT[e+0][r0]   = __float2half(cc[0]);
                    u.b.vT[e+1][r0]   = __float2half(cc[1]);
                    u.b.vT[e+0][r0+8] = __float2half(cc[2]);
                    u.b.vT[e+1][r0+8] = __float2half(cc[3]);
                }
            }
        }
        __syncthreads();
        // Ksum over this subtile, distributed over all 256 threads
        {
            const int d = tid & 63, part = tid >> 6;
            float s = 0.0f;
            #pragma unroll
            for (int n = 0; n < 32; n++) s += __half2float(u.b.kT[d][part*32 + n]);
            ksum += s;
        }
        // KV += kT[64 x 128] @ vT^T
        #pragma unroll
        for (int ks = 0; ks < 8; ks++) {
            uint32_t af[2][4], bq[4];
            #pragma unroll
            for (int mt = 0; mt < 2; mt++)
                ldsm16x16(&u.b.kT[kd0 + mt*16][ks*16], SKT, lane, af[mt]);
            ldsm16x16(&u.b.vT[ke0][ks*16], SKT, lane, bq);
            #pragma unroll
            for (int mt = 0; mt < 2; mt++)
                #pragma unroll
                for (int nt = 0; nt < 2; nt++)
                    mma16816(kvacc[mt][nt],
                             af[mt][0], af[mt][1], af[mt][2], af[mt][3],
                             bq[nt], bq[2 + nt]);
        }
        __syncthreads();
    }
    // write partials
    #pragma unroll
    for (int mt = 0; mt < 2; mt++) {
        const int d = kd0 + mt*16 + g;
        #pragma unroll
        for (int nt = 0; nt < 2; nt++) {
            const int e = ke0 + nt*8 + tig*2;
            g_KV_part[chunk][bh][d  ][e  ] = kvacc[mt][nt][0];
            g_KV_part[chunk][bh][d  ][e+1] = kvacc[mt][nt][1];
            g_KV_part[chunk][bh][d+8][e  ] = kvacc[mt][nt][2];
            g_KV_part[chunk][bh][d+8][e+1] = kvacc[mt][nt][3];
        }
    }
    red[tid] = ksum;
    __syncthreads();
    if (tid < 64)
        g_Ksum_part[chunk][bh][tid] = red[tid] + red[tid+64] + red[tid+128] + red[tid+192];
}

// ===========================================================================
// K2: reduce partials
// ===========================================================================
__global__ __launch_bounds__(256)
void kv_reduce_kernel()
{
    const int idx = blockIdx.x * 256 + threadIdx.x;
    if (idx < NBH*HD*HD) {
        const int bh = idx >> 12, r = idx & 4095;
        float s = 0.0f;
        #pragma unroll
        for (int p = 0; p < KVCH; p++) s += (&g_KV_part[p][bh][0][0])[r];
        (&g_KV[bh][0][0])[r] = s;
    }
    if (idx < NBH*HD) {
        const int bh = idx >> 6, d = idx & 63;
        float s = 0.0f;
        #pragma unroll
        for (int p = 0; p < KVCH; p++) s += g_Ksum_part[p][bh][d];
        g_Ksum[bh][d] = s;
    }
}

// ===========================================================================
// K3: fused q projection (mma) + phi + attn matvec (mma) + normalize.
// Block = (128-token block, bh), 256 threads.
// ===========================================================================
#define SX3 40
#define SQ3 72

struct K3A { __half Xs[128][SX3]; __half Wt[64][SX3]; };
struct K3B { __half qs[128][SQ3]; __half KVt[64][SQ3]; float kss[64]; float den[128]; };

__global__ __launch_bounds__(256, 1)
void q_attn_kernel(const float* __restrict__ x)
{
    __shared__ alignas(16) union { K3A a; K3B b; } u;

    const int tb = blockIdx.x, bh = blockIdx.y;
    const int tid = threadIdx.x, lane = tid & 31, warp = tid >> 5;
    const int g = lane >> 2, tig = lane & 3;
    const int b = bh >> 3, h = bh & 7;
    const int tok0 = tb * 128;

    const int m0 = (warp >> 1) * 32;   // warp grid 4x2, warp tile 32x32
    const int n0 = (warp & 1) * 32;

    const float* xb = x + ((size_t)b*SEQ + tok0) * CDIM;
    const int srow = tid >> 1, sside = (tid & 1) * 16;

    // ---- q projection: 128 x 64, K = 512 ----
    float cacc[2][4][4] = {};
    for (int kc = 0; kc < 16; kc++) {
        {
            const float* src = xb + (size_t)srow*CDIM + kc*32 + sside;
            const float4 v0 = *(const float4*)(src);
            const float4 v1 = *(const float4*)(src + 4);
            const float4 v2 = *(const float4*)(src + 8);
            const float4 v3 = *(const float4*)(src + 12);
            uint4 w0, w1;
            w0.x = f2h2(v0.x, v0.y); w0.y = f2h2(v0.z, v0.w);
            w0.z = f2h2(v1.x, v1.y); w0.w = f2h2(v1.z, v1.w);
            w1.x = f2h2(v2.x, v2.y); w1.y = f2h2(v2.z, v2.w);
            w1.z = f2h2(v3.x, v3.y); w1.w = f2h2(v3.z, v3.w);
            *(uint4*)&u.a.Xs[srow][sside]     = w0;
            *(uint4*)&u.a.Xs[srow][sside + 8] = w1;
        }
        if (tid < 128) {
            const __half* src = &g_WqkvT[h*64 + srow][kc*32 + sside];
            *(uint4*)&u.a.Wt[srow][sside]     = *(const uint4*)(src);
            *(uint4*)&u.a.Wt[srow][sside + 8] = *(const uint4*)(src + 8);
        }
        __syncthreads();
        #pragma unroll
        for (int kh = 0; kh < 2; kh++) {
            uint32_t af[2][4], bq[2][4];
            #pragma unroll
            for (int mt = 0; mt < 2; mt++)
                ldsm16x16(&u.a.Xs[m0 + mt*16][kh*16], SX3, lane, af[mt]);
            #pragma unroll
            for (int np = 0; np < 2; np++)
                ldsm16x16(&u.a.Wt[n0 + np*16][kh*16], SX3, lane, bq[np]);
            #pragma unroll
            for (int mt = 0; mt < 2; mt++)
                #pragma unroll
                for (int nt = 0; nt < 4; nt++)
                    mma16816(cacc[mt][nt],
                             af[mt][0], af[mt][1], af[mt][2], af[mt][3],
                             bq[nt>>1][nt&1], bq[nt>>1][2 + (nt&1)]);
        }
        __syncthreads();
    }
    // ---- epilogue: qs = phi(q) fp16 ; load KV (transposed) + Ksum ----
    #pragma unroll
    for (int mt = 0; mt < 2; mt++) {
        const int r0 = m0 + mt*16 + g;
        #pragma unroll
        for (int nt = 0; nt < 4; nt++) {
            const int c = n0 + nt*8 + tig*2;
            const float* cc = cacc[mt][nt];
            u.b.qs[r0  ][c  ] = __float2half(phi_map(cc[0]));
            u.b.qs[r0  ][c+1] = __float2half(phi_map(cc[1]));
            u.b.qs[r0+8][c  ] = __float2half(phi_map(cc[2]));
            u.b.qs[r0+8][c+1] = __float2half(phi_map(cc[3]));
        }
    }
    {
        #pragma unroll
        for (int i = 0; i < 16; i++) {
            const int lin = tid*16 + i;
            const int d = lin >> 6, e = lin & 63;
            u.b.KVt[e][d] = __float2half(g_KV[bh][d][e]);
        }
        if (tid < 64) u.b.kss[tid] = g_Ksum[bh][tid];
    }
    __syncthreads();
    if (tid < 128) {
        float s = 0.0f;
        #pragma unroll
        for (int d = 0; d < 64; d++) s += __half2float(u.b.qs[tid][d]) * u.b.kss[d];
        u.b.den[tid] = s;
    }
    __syncthreads();
    // ---- attn = qphi @ KV  (K = 64) ----
    float oacc[2][4][4] = {};
    #pragma unroll
    for (int ks = 0; ks < 4; ks++) {
        uint32_t af[2][4], bq[2][4];
        #pragma unroll
        for (int mt = 0; mt < 2; mt++)
            ldsm16x16(&u.b.qs[m0 + mt*16][ks*16], SQ3, lane, af[mt]);
        #pragma unroll
        for (int np = 0; np < 2; np++)
            ldsm16x16(&u.b.KVt[n0 + np*16][ks*16], SQ3, lane, bq[np]);
        #pragma unroll
        for (int mt = 0; mt < 2; mt++)
            #pragma unroll
            for (int nt = 0; nt < 4; nt++)
                mma16816(oacc[mt][nt],
                         af[mt][0], af[mt][1], af[mt][2], af[mt][3],
                         bq[nt>>1][nt&1], bq[nt>>1][2 + (nt&1)]);
    }
    // ---- normalize + fp16 store ----
    #pragma unroll
    for (int mt = 0; mt < 2; mt++) {
        const int r0 = m0 + mt*16 + g;
        const float inv0 = 1.0f / (u.b.den[r0]   + 1e-6f);
        const float inv1 = 1.0f / (u.b.den[r0+8] + 1e-6f);
        #pragma unroll
        for (int nt = 0; nt < 4; nt++) {
            const int c = n0 + nt*8 + tig*2;
            const float* cc = oacc[mt][nt];
            __half2* d0p = (__half2*)&g_attnh[((size_t)(b*SEQ + tok0 + r0  ))*CDIM + h*64 + c];
            __half2* d1p = (__half2*)&g_attnh[((size_t)(b*SEQ + tok0 + r0+8))*CDIM + h*64 + c];
            *d0p = __floats2half2_rn(cc[0]*inv0, cc[1]*inv0);
            *d1p = __floats2half2_rn(cc[2]*inv1, cc[3]*inv1);
        }
    }
}

// ===========================================================================
// K4: out = attnh(fp16) @ W_out + bias  (mma), 128x128 tile.
// ===========================================================================
#define SX4 40

__global__ __launch_bounds__(256, 1)
void out_proj_kernel(const float* __restrict__ bias,
                     float* __restrict__ Cout)
{
    __shared__ alignas(16) __half Xs[128][SX4];
    __shared__ alignas(16) __half Wt[128][SX4];

    const int tid = threadIdx.x, lane = tid & 31, warp = tid >> 5;
    const int g = lane >> 2, tig = lane & 3;
    const int brow = blockIdx.x, bcol = blockIdx.y;
    const int m0 = (warp >> 1) * 32;
    const int n0w = (warp & 1) * 64;
    const int srow = tid >> 1, sside = (tid & 1) * 16;

    float cacc[2][8][4] = {};
    for (int kc = 0; kc < 16; kc++) {
        {   // A: already fp16
            const __half* src = g_attnh + (size_t)(brow*128 + srow)*CDIM + kc*32 + sside;
            *(uint4*)&Xs[srow][sside]     = *(const uint4*)(src);
            *(uint4*)&Xs[srow][sside + 8] = *(const uint4*)(src + 8);
        }
        {   // B: pre-transposed fp16 weights
            const __half* src = &g_WoutT[bcol*128 + srow][kc*32 + sside];
            *(uint4*)&Wt[srow][sside]     = *(const uint4*)(src);
            *(uint4*)&Wt[srow][sside + 8] = *(const uint4*)(src + 8);
        }
        __syncthreads();
        #pragma unroll
        for (int kh = 0; kh < 2; kh++) {
            uint32_t af[2][4], bq[4][4];
            #pragma unroll
            for (int mt = 0; mt < 2; mt++)
                ldsm16x16(&Xs[m0 + mt*16][kh*16], SX4, lane, af[mt]);
            #pragma unroll
            for (int np = 0; np < 4; np++)
                ldsm16x16(&Wt[n0w + np*16][kh*16], SX4, lane, bq[np]);
            #pragma unroll
            for (int mt = 0; mt < 2; mt++)
                #pragma unroll
                for (int nt = 0; nt < 8; nt++)
                    mma16816(cacc[mt][nt],
                             af[mt][0], af[mt][1], af[mt][2], af[mt][3],
                             bq[nt>>1][nt&1], bq[nt>>1][2 + (nt&1)]);
        }
        __syncthreads();
    }
    #pragma unroll
    for (int mt = 0; mt < 2; mt++) {
        const int r0 = brow*128 + m0 + mt*16 + g;
        #pragma unroll
        for (int nt = 0; nt < 8; nt++) {
            const int c = bcol*128 + n0w + nt*8 + tig*2;
            const float2 bv = *(const float2*)&bias[c];
            const float* cc = cacc[mt][nt];
            float2 o0 = { cc[0] + bv.x, cc[1] + bv.y };
            float2 o1 = { cc[2] + bv.x, cc[3] + bv.y };
            *(float2*)&Cout[(size_t)r0*CDIM + c]     = o0;
            *(float2*)&Cout[(size_t)(r0+8)*CDIM + c] = o1;
        }
    }
}

// ===========================================================================
extern "C" void kernel_launch(void* const* d_in, const int* in_sizes, int n_in,
                              void* d_out, int out_size)
{
    const float* x     = (const float*)d_in[0];
    const float* W_qkv = (const float*)d_in[1];
    const float* W_out = (const float*)d_in[2];
    const float* b_out = (const float*)d_in[3];
    float* out = (float*)d_out;

    // K0: weight transposes (fp32 -> fp16, k-contiguous)
    {   __half* wqkvT = nullptr; cudaGetSymbolAddress((void**)&wqkvT, g_WqkvT);
        __half* woutT = nullptr; cudaGetSymbolAddress((void**)&woutT, g_WoutT);
        transpose_w_kernel<<<dim3(3*CDIM/32, CDIM/32), 256>>>(W_qkv, wqkvT, CDIM, 3*CDIM);
        transpose_w_kernel<<<dim3(CDIM/32, CDIM/32),   256>>>(W_out, woutT, CDIM, CDIM);
    }
    {   dim3 grid(NBH, KVCH);                 // 64 x 8
        kv_build_kernel<<<grid, 256>>>(x); }
    kv_reduce_kernel<<<(NBH*HD*HD + 255)/256, 256>>>();
    {   dim3 grid(SEQ/128, NBH);              // 32 x 64
        q_attn_kernel<<<grid, 256>>>(x); }
    {   dim3 grid(MROWS/128, CDIM/128);       // 256 x 4
        out_proj_kernel<<<grid, 256>>>(b_out, out); }
}

// round 9
// speedup vs baseline: 7.9070x; 1.2879x over previous
#include <cuda_runtime.h>
#include <cuda_fp16.h>
#include <cstdint>
#include <math.h>

#define BB   8
#define SEQ  4096
#define CDIM 512
#define NH   8
#define HD   64
#define MROWS (BB*SEQ)   // 32768
#define NBH  (BB*NH)     // 64
#define KVCH 8

// ---------------- static device scratch (~44 MB, known-safe) ---------------
__device__ float  g_KV_part[KVCH][NBH][HD][HD];
__device__ float  g_Ksum_part[KVCH][NBH][HD];
__device__ float  g_KV[NBH][HD][HD];
__device__ float  g_Ksum[NBH][HD];
__device__ __half g_attnh[(size_t)MROWS*CDIM];    // 32 MB
__device__ __half g_WqkvT[3*CDIM][CDIM];          // 1.5 MB  [out_col][k]
__device__ __half g_WoutT[CDIM][CDIM];            // 0.5 MB  [out_col][k]

__device__ __forceinline__ float phi_map(float x) {
    return x > 0.0f ? x + 1.0f : __expf(x);
}
__device__ __forceinline__ uint32_t f2h2(float a, float b) {
    __half2 h = __floats2half2_rn(a, b);
    return *reinterpret_cast<uint32_t*>(&h);
}

// ---- cp.async helpers ------------------------------------------------------
__device__ __forceinline__ void cp16(void* dst, const void* src) {
    uint32_t d = (uint32_t)__cvta_generic_to_shared(dst);
    asm volatile("cp.async.cg.shared.global [%0], [%1], 16;" :: "r"(d), "l"(src));
}
__device__ __forceinline__ void cp_commit() { asm volatile("cp.async.commit_group;" ::: "memory"); }
__device__ __forceinline__ void cp_wait0()  { asm volatile("cp.async.wait_group 0;" ::: "memory"); }
__device__ __forceinline__ void cp_wait1()  { asm volatile("cp.async.wait_group 1;" ::: "memory"); }

// ---- mma.sync m16n8k16 fp16 -> fp32 ---------------------------------------
__device__ __forceinline__ void mma16816(float* c,
    uint32_t a0, uint32_t a1, uint32_t a2, uint32_t a3,
    uint32_t b0, uint32_t b1)
{
    asm volatile(
        "mma.sync.aligned.m16n8k16.row.col.f32.f16.f16.f32 "
        "{%0,%1,%2,%3},{%4,%5,%6,%7},{%8,%9},{%0,%1,%2,%3};"
        : "+f"(c[0]), "+f"(c[1]), "+f"(c[2]), "+f"(c[3])
        : "r"(a0), "r"(a1), "r"(a2), "r"(a3), "r"(b0), "r"(b1));
}

// ldmatrix x4 of a 16x16 fp16 tile at (row0, k0), row stride S halves.
__device__ __forceinline__ void ldsm16x16(const __half* tile, int S, int lane, uint32_t* r) {
    const int t = lane >> 3, j = lane & 7;
    const __half* addr = tile + (size_t)(((t & 1) << 3) + j) * S + ((t >> 1) << 3);
    uint32_t a = (uint32_t)__cvta_generic_to_shared(addr);
    asm volatile("ldmatrix.sync.aligned.m8n8.x4.shared.b16 {%0,%1,%2,%3}, [%4];"
                 : "=r"(r[0]), "=r"(r[1]), "=r"(r[2]), "=r"(r[3]) : "r"(a));
}

// pack 16 fp32 (4 float4) -> 2 uint4 of halves, store to smem row
__device__ __forceinline__ void cvt_sts16(__half* dst, const float4* v) {
    uint4 w0, w1;
    w0.x = f2h2(v[0].x, v[0].y); w0.y = f2h2(v[0].z, v[0].w);
    w0.z = f2h2(v[1].x, v[1].y); w0.w = f2h2(v[1].z, v[1].w);
    w1.x = f2h2(v[2].x, v[2].y); w1.y = f2h2(v[2].z, v[2].w);
    w1.z = f2h2(v[3].x, v[3].y); w1.w = f2h2(v[3].z, v[3].w);
    *(uint4*)(dst)     = w0;
    *(uint4*)(dst + 8) = w1;
}

// ===========================================================================
// K0: W[R][C] fp32  ->  WT[C][R] fp16
// ===========================================================================
__global__ __launch_bounds__(256)
void transpose_w_kernel(const float* __restrict__ W, __half* __restrict__ WT,
                        int R, int C)
{
    __shared__ __half ts[32][33];
    const int tid = threadIdx.x;
    const int r = tid >> 3, c4 = (tid & 7) * 4;
    const float* src = W + (size_t)(blockIdx.y*32 + r)*C + blockIdx.x*32 + c4;
    const float4 v = *(const float4*)src;
    ts[c4+0][r] = __float2half(v.x);
    ts[c4+1][r] = __float2half(v.y);
    ts[c4+2][r] = __float2half(v.z);
    ts[c4+3][r] = __float2half(v.w);
    __syncthreads();
    __half* dst = WT + (size_t)(blockIdx.x*32 + r)*R + blockIdx.y*32 + c4;
    dst[0] = ts[r][c4+0]; dst[1] = ts[r][c4+1];
    dst[2] = ts[r][c4+2]; dst[3] = ts[r][c4+3];
}

// ===========================================================================
// K1: fused k/v projection (mma, pipelined) + KV/Ksum accumulation (mma).
// Block = (bh, chunk of 512 tokens), 256 threads (8 warps).
// ===========================================================================
#define SX1 40
#define SKT 136

struct K1Stage { __half Xs[128][SX1]; __half Wt[128][SX1]; };   // 20480 B
struct K1B     { __half kT[64][SKT];  __half vT[64][SKT];  };   // 34816 B

__global__ __launch_bounds__(256, 1)
void kv_build_kernel(const float* __restrict__ x)
{
    __shared__ alignas(16) union { K1Stage s[2]; K1B b; } u;    // 40960 B
    __shared__ float red[256];

    const int bh = blockIdx.x, chunk = blockIdx.y;
    const int tid = threadIdx.x, lane = tid & 31, warp = tid >> 5;
    const int g = lane >> 2, tig = lane & 3;
    const int b = bh >> 3, h = bh & 7;

    const int pm0 = (warp >> 1) * 32;      // proj warp grid 4x2
    const int pni = warp & 1;
    const int pn0 = pni * 64;
    const int kd0 = (warp >> 2) * 32;      // KV warp grid 2x4
    const int ke0 = (warp & 3) * 16;

    float kvacc[2][2][4] = {};
    float ksum = 0.0f;

    const float* xb = x + ((size_t)b*SEQ + chunk*512) * CDIM;
    const int srow = tid >> 1, sside = (tid & 1) * 16;
    const int wgn = (srow < 64) ? (512 + h*64 + srow) : (1024 + h*64 + (srow - 64));
    const __half* wrow = g_WqkvT[wgn];

    for (int st = 0; st < 4; st++) {
        float cacc[2][8][4] = {};
        const float* xrow = xb + (size_t)(st*128 + srow)*CDIM + sside;

        // ---- pipeline prologue: x(0) -> regs, W(0) -> cp.async ----
        float4 xr[4], xn[4];
        xr[0] = *(const float4*)(xrow);      xr[1] = *(const float4*)(xrow + 4);
        xr[2] = *(const float4*)(xrow + 8);  xr[3] = *(const float4*)(xrow + 12);
        cp16(&u.s[0].Wt[srow][sside],     wrow + sside);
        cp16(&u.s[0].Wt[srow][sside + 8], wrow + sside + 8);
        cp_commit();

        for (int kc = 0; kc < 16; kc++) {
            const int cur = kc & 1;
            cvt_sts16(&u.s[cur].Xs[srow][sside], xr);
            if (kc < 15) {
                const float* nsrc = xrow + (kc+1)*32;
                xn[0] = *(const float4*)(nsrc);      xn[1] = *(const float4*)(nsrc + 4);
                xn[2] = *(const float4*)(nsrc + 8);  xn[3] = *(const float4*)(nsrc + 12);
                const __half* wsrc = wrow + (kc+1)*32 + sside;
                cp16(&u.s[cur^1].Wt[srow][sside],     wsrc);
                cp16(&u.s[cur^1].Wt[srow][sside + 8], wsrc + 8);
                cp_commit();
                cp_wait1();
            } else {
                cp_wait0();
            }
            __syncthreads();
            #pragma unroll
            for (int kh = 0; kh < 2; kh++) {
                uint32_t af[2][4], bq[4][4];
                #pragma unroll
                for (int mt = 0; mt < 2; mt++)
                    ldsm16x16(&u.s[cur].Xs[pm0 + mt*16][kh*16], SX1, lane, af[mt]);
                #pragma unroll
                for (int np = 0; np < 4; np++)
                    ldsm16x16(&u.s[cur].Wt[pn0 + np*16][kh*16], SX1, lane, bq[np]);
                #pragma unroll
                for (int mt = 0; mt < 2; mt++)
                    #pragma unroll
                    for (int nt = 0; nt < 8; nt++)
                        mma16816(cacc[mt][nt],
                                 af[mt][0], af[mt][1], af[mt][2], af[mt][3],
                                 bq[nt>>1][nt&1], bq[nt>>1][2 + (nt&1)]);
            }
            __syncthreads();
            xr[0]=xn[0]; xr[1]=xn[1]; xr[2]=xn[2]; xr[3]=xn[3];
        }

        // ---- epilogue: phi + transposed fp16 store into kT/vT (aliases stages) ----
        #pragma unroll
        for (int mt = 0; mt < 2; mt++) {
            const int r0 = pm0 + mt*16 + g;
            #pragma unroll
            for (int nt = 0; nt < 8; nt++) {
                const int c = pn0 + nt*8 + tig*2;
                const float* cc = cacc[mt][nt];
                if (pni == 0) {
                    u.b.kT[c+0][r0]   = __float2half(phi_map(cc[0]));
                    u.b.kT[c+1][r0]   = __float2half(phi_map(cc[1]));
                    u.b.kT[c+0][r0+8] = __float2half(phi_map(cc[2]));
                    u.b.kT[c+1][r0+8] = __float2half(phi_map(cc[3]));
                } else {
                    const int e = c - 64;
                    u.b.vT[e+0][r0]   = __float2half(cc[0]);
                    u.b.vT[e+1][r0]   = __float2half(cc[1]);
                    u.b.vT[e+0][r0+8] = __float2half(cc[2]);
                    u.b.vT[e+1][r0+8] = __float2half(cc[3]);
                }
            }
        }
        __syncthreads();
        {   // Ksum distributed over 256 threads
            const int d = tid & 63, part = tid >> 6;
            float s = 0.0f;
            #pragma unroll
            for (int n = 0; n < 32; n++) s += __half2float(u.b.kT[d][part*32 + n]);
            ksum += s;
        }
        // KV += kT[64 x 128] @ vT^T
        #pragma unroll
        for (int ks = 0; ks < 8; ks++) {
            uint32_t af[2][4], bq[4];
            #pragma unroll
            for (int mt = 0; mt < 2; mt++)
                ldsm16x16(&u.b.kT[kd0 + mt*16][ks*16], SKT, lane, af[mt]);
            ldsm16x16(&u.b.vT[ke0][ks*16], SKT, lane, bq);
            #pragma unroll
            for (int mt = 0; mt < 2; mt++)
                #pragma unroll
                for (int nt = 0; nt < 2; nt++)
                    mma16816(kvacc[mt][nt],
                             af[mt][0], af[mt][1], af[mt][2], af[mt][3],
                             bq[nt], bq[2 + nt]);
        }
        __syncthreads();
    }
    // write partials
    #pragma unroll
    for (int mt = 0; mt < 2; mt++) {
        const int d = kd0 + mt*16 + g;
        #pragma unroll
        for (int nt = 0; nt < 2; nt++) {
            const int e = ke0 + nt*8 + tig*2;
            g_KV_part[chunk][bh][d  ][e  ] = kvacc[mt][nt][0];
            g_KV_part[chunk][bh][d  ][e+1] = kvacc[mt][nt][1];
            g_KV_part[chunk][bh][d+8][e  ] = kvacc[mt][nt][2];
            g_KV_part[chunk][bh][d+8][e+1] = kvacc[mt][nt][3];
        }
    }
    red[tid] = ksum;
    __syncthreads();
    if (tid < 64)
        g_Ksum_part[chunk][bh][tid] = red[tid] + red[tid+64] + red[tid+128] + red[tid+192];
}

// ===========================================================================
// K2: reduce partials
// ===========================================================================
__global__ __launch_bounds__(256)
void kv_reduce_kernel()
{
    const int idx = blockIdx.x * 256 + threadIdx.x;
    if (idx < NBH*HD*HD) {
        const int bh = idx >> 12, r = idx & 4095;
        float s = 0.0f;
        #pragma unroll
        for (int p = 0; p < KVCH; p++) s += (&g_KV_part[p][bh][0][0])[r];
        (&g_KV[bh][0][0])[r] = s;
    }
    if (idx < NBH*HD) {
        const int bh = idx >> 6, d = idx & 63;
        float s = 0.0f;
        #pragma unroll
        for (int p = 0; p < KVCH; p++) s += g_Ksum_part[p][bh][d];
        g_Ksum[bh][d] = s;
    }
}

// ===========================================================================
// K3: fused q projection (mma, pipelined) + phi + attn matvec + normalize.
// Block = (bh, 128-token block) -- bh fastest for L2 reuse of x tiles.
// ===========================================================================
#define SX3 40
#define SQ3 72

struct K3Stage { __half Xs[128][SX3]; __half Wt[64][SX3]; };    // 15360 B
struct K3B { __half qs[128][SQ3]; __half KVt[64][SQ3]; float kss[64]; float den[128]; };

__global__ __launch_bounds__(256, 1)
void q_attn_kernel(const float* __restrict__ x)
{
    __shared__ alignas(16) union { K3Stage s[2]; K3B b; } u;    // 30720 B

    const int bh = blockIdx.x, tb = blockIdx.y;
    const int tid = threadIdx.x, lane = tid & 31, warp = tid >> 5;
    const int g = lane >> 2, tig = lane & 3;
    const int b = bh >> 3, h = bh & 7;
    const int tok0 = tb * 128;

    const int m0 = (warp >> 1) * 32;
    const int n0 = (warp & 1) * 32;

    const float* xb = x + ((size_t)b*SEQ + tok0) * CDIM;
    const int srow = tid >> 1, sside = (tid & 1) * 16;
    const float* xrow = xb + (size_t)srow*CDIM + sside;
    const __half* wrow = g_WqkvT[h*64 + (tid >> 2)];   // 64 rows staged by tids 0..255 (4/row)
    const int wside = (tid & 3) * 8;                   // 8 halves per thread

    // ---- q projection: 128 x 64, K=512, 2-stage pipeline ----
    float cacc[2][4][4] = {};
    float4 xr[4], xn[4];
    xr[0] = *(const float4*)(xrow);      xr[1] = *(const float4*)(xrow + 4);
    xr[2] = *(const float4*)(xrow + 8);  xr[3] = *(const float4*)(xrow + 12);
    cp16(&u.s[0].Wt[tid >> 2][wside], wrow + wside);
    cp_commit();

    for (int kc = 0; kc < 16; kc++) {
        const int cur = kc & 1;
        cvt_sts16(&u.s[cur].Xs[srow][sside], xr);
        if (kc < 15) {
            const float* nsrc = xrow + (kc+1)*32;
            xn[0] = *(const float4*)(nsrc);      xn[1] = *(const float4*)(nsrc + 4);
            xn[2] = *(const float4*)(nsrc + 8);  xn[3] = *(const float4*)(nsrc + 12);
            cp16(&u.s[cur^1].Wt[tid >> 2][wside], wrow + (kc+1)*32 + wside);
            cp_commit();
            cp_wait1();
        } else {
            cp_wait0();
        }
        __syncthreads();
        #pragma unroll
        for (int kh = 0; kh < 2; kh++) {
            uint32_t af[2][4], bq[2][4];
            #pragma unroll
            for (int mt = 0; mt < 2; mt++)
                ldsm16x16(&u.s[cur].Xs[m0 + mt*16][kh*16], SX3, lane, af[mt]);
            #pragma unroll
            for (int np = 0; np < 2; np++)
                ldsm16x16(&u.s[cur].Wt[n0 + np*16][kh*16], SX3, lane, bq[np]);
            #pragma unroll
            for (int mt = 0; mt < 2; mt++)
                #pragma unroll
                for (int nt = 0; nt < 4; nt++)
                    mma16816(cacc[mt][nt],
                             af[mt][0], af[mt][1], af[mt][2], af[mt][3],
                             bq[nt>>1][nt&1], bq[nt>>1][2 + (nt&1)]);
        }
        __syncthreads();
        xr[0]=xn[0]; xr[1]=xn[1]; xr[2]=xn[2]; xr[3]=xn[3];
    }

    // ---- epilogue: qs = phi(q) fp16 ; load KV (transposed) + Ksum ----
    #pragma unroll
    for (int mt = 0; mt < 2; mt++) {
        const int r0 = m0 + mt*16 + g;
        #pragma unroll
        for (int nt = 0; nt < 4; nt++) {
            const int c = n0 + nt*8 + tig*2;
            const float* cc = cacc[mt][nt];
            u.b.qs[r0  ][c  ] = __float2half(phi_map(cc[0]));
            u.b.qs[r0  ][c+1] = __float2half(phi_map(cc[1]));
            u.b.qs[r0+8][c  ] = __float2half(phi_map(cc[2]));
            u.b.qs[r0+8][c+1] = __float2half(phi_map(cc[3]));
        }
    }
    {
        #pragma unroll
        for (int i = 0; i < 16; i++) {
            const int lin = tid*16 + i;
            const int d = lin >> 6, e = lin & 63;
            u.b.KVt[e][d] = __float2half(g_KV[bh][d][e]);
        }
        if (tid < 64) u.b.kss[tid] = g_Ksum[bh][tid];
    }
    __syncthreads();
    if (tid < 128) {
        float s = 0.0f;
        #pragma unroll
        for (int d = 0; d < 64; d++) s += __half2float(u.b.qs[tid][d]) * u.b.kss[d];
        u.b.den[tid] = s;
    }
    __syncthreads();
    // ---- attn = qphi @ KV  (K = 64) ----
    float oacc[2][4][4] = {};
    #pragma unroll
    for (int ks = 0; ks < 4; ks++) {
        uint32_t af[2][4], bq[2][4];
        #pragma unroll
        for (int mt = 0; mt < 2; mt++)
            ldsm16x16(&u.b.qs[m0 + mt*16][ks*16], SQ3, lane, af[mt]);
        #pragma unroll
        for (int np = 0; np < 2; np++)
            ldsm16x16(&u.b.KVt[n0 + np*16][ks*16], SQ3, lane, bq[np]);
        #pragma unroll
        for (int mt = 0; mt < 2; mt++)
            #pragma unroll
            for (int nt = 0; nt < 4; nt++)
                mma16816(oacc[mt][nt],
                         af[mt][0], af[mt][1], af[mt][2], af[mt][3],
                         bq[nt>>1][nt&1], bq[nt>>1][2 + (nt&1)]);
    }
    // ---- normalize + fp16 store ----
    #pragma unroll
    for (int mt = 0; mt < 2; mt++) {
        const int r0 = m0 + mt*16 + g;
        const float inv0 = 1.0f / (u.b.den[r0]   + 1e-6f);
        const float inv1 = 1.0f / (u.b.den[r0+8] + 1e-6f);
        #pragma unroll
        for (int nt = 0; nt < 4; nt++) {
            const int c = n0 + nt*8 + tig*2;
            const float* cc = oacc[mt][nt];
            __half2* d0p = (__half2*)&g_attnh[((size_t)(b*SEQ + tok0 + r0  ))*CDIM + h*64 + c];
            __half2* d1p = (__half2*)&g_attnh[((size_t)(b*SEQ + tok0 + r0+8))*CDIM + h*64 + c];
            *d0p = __floats2half2_rn(cc[0]*inv0, cc[1]*inv0);
            *d1p = __floats2half2_rn(cc[2]*inv1, cc[3]*inv1);
        }
    }
}

// ===========================================================================
// K4: out = attnh(fp16) @ W_out + bias -- fully cp.async double-buffered.
// ===========================================================================
#define SX4 40

struct K4Stage { __half Xs[128][SX4]; __half Wt[128][SX4]; };   // 20480 B

__global__ __launch_bounds__(256, 1)
void out_proj_kernel(const float* __restrict__ bias,
                     float* __restrict__ Cout)
{
    __shared__ alignas(16) K4Stage s[2];                         // 40960 B

    const int tid = threadIdx.x, lane = tid & 31, warp = tid >> 5;
    const int g = lane >> 2, tig = lane & 3;
    const int brow = blockIdx.x, bcol = blockIdx.y;
    const int m0 = (warp >> 1) * 32;
    const int n0w = (warp & 1) * 64;
    const int srow = tid >> 1, sside = (tid & 1) * 16;

    const __half* arow = g_attnh + (size_t)(brow*128 + srow)*CDIM + sside;
    const __half* wrow = &g_WoutT[bcol*128 + srow][sside];

    // prologue
    cp16(&s[0].Xs[srow][sside],     arow);
    cp16(&s[0].Xs[srow][sside + 8], arow + 8);
    cp16(&s[0].Wt[srow][sside],     wrow);
    cp16(&s[0].Wt[srow][sside + 8], wrow + 8);
    cp_commit();

    float cacc[2][8][4] = {};
    for (int kc = 0; kc < 16; kc++) {
        const int cur = kc & 1;
        if (kc < 15) {
            const __half* an = arow + (kc+1)*32;
            const __half* wn = wrow + (kc+1)*32;
            cp16(&s[cur^1].Xs[srow][sside],     an);
            cp16(&s[cur^1].Xs[srow][sside + 8], an + 8);
            cp16(&s[cur^1].Wt[srow][sside],     wn);
            cp16(&s[cur^1].Wt[srow][sside + 8], wn + 8);
            cp_commit();
            cp_wait1();
        } else {
            cp_wait0();
        }
        __syncthreads();
        #pragma unroll
        for (int kh = 0; kh < 2; kh++) {
            uint32_t af[2][4], bq[4][4];
            #pragma unroll
            for (int mt = 0; mt < 2; mt++)
                ldsm16x16(&s[cur].Xs[m0 + mt*16][kh*16], SX4, lane, af[mt]);
            #pragma unroll
            for (int np = 0; np < 4; np++)
                ldsm16x16(&s[cur].Wt[n0w + np*16][kh*16], SX4, lane, bq[np]);
            #pragma unroll
            for (int mt = 0; mt < 2; mt++)
                #pragma unroll
                for (int nt = 0; nt < 8; nt++)
                    mma16816(cacc[mt][nt],
                             af[mt][0], af[mt][1], af[mt][2], af[mt][3],
                             bq[nt>>1][nt&1], bq[nt>>1][2 + (nt&1)]);
        }
        __syncthreads();
    }
    #pragma unroll
    for (int mt = 0; mt < 2; mt++) {
        const int r0 = brow*128 + m0 + mt*16 + g;
        #pragma unroll
        for (int nt = 0; nt < 8; nt++) {
            const int c = bcol*128 + n0w + nt*8 + tig*2;
            const float2 bv = *(const float2*)&bias[c];
            const float* cc = cacc[mt][nt];
            float2 o0 = { cc[0] + bv.x, cc[1] + bv.y };
            float2 o1 = { cc[2] + bv.x, cc[3] + bv.y };
            *(float2*)&Cout[(size_t)r0*CDIM + c]     = o0;
            *(float2*)&Cout[(size_t)(r0+8)*CDIM + c] = o1;
        }
    }
}

// ===========================================================================
extern "C" void kernel_launch(void* const* d_in, const int* in_sizes, int n_in,
                              void* d_out, int out_size)
{
    const float* x     = (const float*)d_in[0];
    const float* W_qkv = (const float*)d_in[1];
    const float* W_out = (const float*)d_in[2];
    const float* b_out = (const float*)d_in[3];
    float* out = (float*)d_out;

    {   __half* wqkvT = nullptr; cudaGetSymbolAddress((void**)&wqkvT, g_WqkvT);
        __half* woutT = nullptr; cudaGetSymbolAddress((void**)&woutT, g_WoutT);
        transpose_w_kernel<<<dim3(3*CDIM/32, CDIM/32), 256>>>(W_qkv, wqkvT, CDIM, 3*CDIM);
        transpose_w_kernel<<<dim3(CDIM/32, CDIM/32),   256>>>(W_out, woutT, CDIM, CDIM);
    }
    {   dim3 grid(NBH, KVCH);                 // 64 x 8
        kv_build_kernel<<<grid, 256>>>(x); }
    kv_reduce_kernel<<<(NBH*HD*HD + 255)/256, 256>>>();
    {   dim3 grid(NBH, SEQ/128);              // 64 x 32  (bh fastest -> L2 reuse)
        q_attn_kernel<<<grid, 256>>>(x); }
    {   dim3 grid(MROWS/128, CDIM/128);       // 256 x 4
        out_proj_kernel<<<grid, 256>>>(b_out, out); }
}

// round 11
// speedup vs baseline: 8.0335x; 1.0160x over previous
#include <cuda_runtime.h>
#include <cuda_fp16.h>
#include <cstdint>
#include <math.h>

#define BB   8
#define SEQ  4096
#define CDIM 512
#define NH   8
#define HD   64
#define MROWS (BB*SEQ)   // 32768
#define NBH  (BB*NH)     // 64
#define KVCH 8

// ---------------- static device scratch (~44 MB, known-safe) ---------------
__device__ float  g_KV_part[KVCH][NBH][HD][HD];
__device__ float  g_Ksum_part[KVCH][NBH][HD];
__device__ float  g_KV[NBH][HD][HD];
__device__ float  g_Ksum[NBH][HD];
__device__ __half g_attnh[(size_t)MROWS*CDIM];    // 32 MB
__device__ __half g_WqkvT[3*CDIM][CDIM];          // 1.5 MB  [out_col][k]
__device__ __half g_WoutT[CDIM][CDIM];            // 0.5 MB  [out_col][k]

__device__ __forceinline__ float phi_map(float x) {
    return x > 0.0f ? x + 1.0f : __expf(x);
}
__device__ __forceinline__ uint32_t f2h2(float a, float b) {
    __half2 h = __floats2half2_rn(a, b);
    return *reinterpret_cast<uint32_t*>(&h);
}

// ---- cp.async helpers ------------------------------------------------------
__device__ __forceinline__ void cp16(void* dst, const void* src) {
    uint32_t d = (uint32_t)__cvta_generic_to_shared(dst);
    asm volatile("cp.async.cg.shared.global [%0], [%1], 16;" :: "r"(d), "l"(src));
}
__device__ __forceinline__ void cp_commit() { asm volatile("cp.async.commit_group;" ::: "memory"); }
__device__ __forceinline__ void cp_wait0()  { asm volatile("cp.async.wait_group 0;" ::: "memory"); }
__device__ __forceinline__ void cp_wait1()  { asm volatile("cp.async.wait_group 1;" ::: "memory"); }

// ---- mma.sync m16n8k16 fp16 -> fp32 ---------------------------------------
__device__ __forceinline__ void mma16816(float* c,
    uint32_t a0, uint32_t a1, uint32_t a2, uint32_t a3,
    uint32_t b0, uint32_t b1)
{
    asm volatile(
        "mma.sync.aligned.m16n8k16.row.col.f32.f16.f16.f32 "
        "{%0,%1,%2,%3},{%4,%5,%6,%7},{%8,%9},{%0,%1,%2,%3};"
        : "+f"(c[0]), "+f"(c[1]), "+f"(c[2]), "+f"(c[3])
        : "r"(a0), "r"(a1), "r"(a2), "r"(a3), "r"(b0), "r"(b1));
}

// ldmatrix x4 of a 16x16 fp16 tile at (row0, k0), row stride S halves.
__device__ __forceinline__ void ldsm16x16(const __half* tile, int S, int lane, uint32_t* r) {
    const int t = lane >> 3, j = lane & 7;
    const __half* addr = tile + (size_t)(((t & 1) << 3) + j) * S + ((t >> 1) << 3);
    uint32_t a = (uint32_t)__cvta_generic_to_shared(addr);
    asm volatile("ldmatrix.sync.aligned.m8n8.x4.shared.b16 {%0,%1,%2,%3}, [%4];"
                 : "=r"(r[0]), "=r"(r[1]), "=r"(r[2]), "=r"(r[3]) : "r"(a));
}

// pack 16 fp32 (4 float4) -> 2 uint4 of halves, store to smem row
__device__ __forceinline__ void cvt_sts16(__half* dst, const float4* v) {
    uint4 w0, w1;
    w0.x = f2h2(v[0].x, v[0].y); w0.y = f2h2(v[0].z, v[0].w);
    w0.z = f2h2(v[1].x, v[1].y); w0.w = f2h2(v[1].z, v[1].w);
    w1.x = f2h2(v[2].x, v[2].y); w1.y = f2h2(v[2].z, v[2].w);
    w1.z = f2h2(v[3].x, v[3].y); w1.w = f2h2(v[3].z, v[3].w);
    *(uint4*)(dst)     = w0;
    *(uint4*)(dst + 8) = w1;
}

// ===========================================================================
// K0: W[R][C] fp32  ->  WT[C][R] fp16
// ===========================================================================
__global__ __launch_bounds__(256)
void transpose_w_kernel(const float* __restrict__ W, __half* __restrict__ WT,
                        int R, int C)
{
    __shared__ __half ts[32][33];
    const int tid = threadIdx.x;
    const int r = tid >> 3, c4 = (tid & 7) * 4;
    const float* src = W + (size_t)(blockIdx.y*32 + r)*C + blockIdx.x*32 + c4;
    const float4 v = *(const float4*)src;
    ts[c4+0][r] = __float2half(v.x);
    ts[c4+1][r] = __float2half(v.y);
    ts[c4+2][r] = __float2half(v.z);
    ts[c4+3][r] = __float2half(v.w);
    __syncthreads();
    __half* dst = WT + (size_t)(blockIdx.x*32 + r)*R + blockIdx.y*32 + c4;
    dst[0] = ts[r][c4+0]; dst[1] = ts[r][c4+1];
    dst[2] = ts[r][c4+2]; dst[3] = ts[r][c4+3];
}

// ===========================================================================
// K1: fused k/v projection (mma, pipelined) + KV/Ksum accumulation (mma).
// Block = (bh, chunk of 512 tokens), 256 threads (8 warps).
// ===========================================================================
#define SX1 40
#define SKT 136

struct K1Stage { __half Xs[128][SX1]; __half Wt[128][SX1]; };   // 20480 B
struct K1B     { __half kT[64][SKT];  __half vT[64][SKT];  };   // 34816 B

__global__ __launch_bounds__(256, 1)
void kv_build_kernel(const float* __restrict__ x)
{
    __shared__ alignas(16) union { K1Stage s[2]; K1B b; } u;    // 40960 B
    __shared__ float red[256];

    const int bh = blockIdx.x, chunk = blockIdx.y;
    const int tid = threadIdx.x, lane = tid & 31, warp = tid >> 5;
    const int g = lane >> 2, tig = lane & 3;
    const int b = bh >> 3, h = bh & 7;

    const int pm0 = (warp >> 1) * 32;      // proj warp grid 4x2
    const int pni = warp & 1;
    const int pn0 = pni * 64;
    const int kd0 = (warp >> 2) * 32;      // KV warp grid 2x4
    const int ke0 = (warp & 3) * 16;

    float kvacc[2][2][4] = {};
    float ksum = 0.0f;

    const float* xb = x + ((size_t)b*SEQ + chunk*512) * CDIM;
    const int srow = tid >> 1, sside = (tid & 1) * 16;
    const int wgn = (srow < 64) ? (512 + h*64 + srow) : (1024 + h*64 + (srow - 64));
    const __half* wrow = g_WqkvT[wgn];

    for (int st = 0; st < 4; st++) {
        float cacc[2][8][4] = {};
        const float* xrow = xb + (size_t)(st*128 + srow)*CDIM + sside;

        float4 xr[4], xn[4];
        xr[0] = *(const float4*)(xrow);      xr[1] = *(const float4*)(xrow + 4);
        xr[2] = *(const float4*)(xrow + 8);  xr[3] = *(const float4*)(xrow + 12);
        cp16(&u.s[0].Wt[srow][sside],     wrow + sside);
        cp16(&u.s[0].Wt[srow][sside + 8], wrow + sside + 8);
        cp_commit();

        for (int kc = 0; kc < 16; kc++) {
            const int cur = kc & 1;
            cvt_sts16(&u.s[cur].Xs[srow][sside], xr);
            if (kc < 15) {
                const float* nsrc = xrow + (kc+1)*32;
                xn[0] = *(const float4*)(nsrc);      xn[1] = *(const float4*)(nsrc + 4);
                xn[2] = *(const float4*)(nsrc + 8);  xn[3] = *(const float4*)(nsrc + 12);
                const __half* wsrc = wrow + (kc+1)*32 + sside;
                cp16(&u.s[cur^1].Wt[srow][sside],     wsrc);
                cp16(&u.s[cur^1].Wt[srow][sside + 8], wsrc + 8);
                cp_commit();
                cp_wait1();
            } else {
                cp_wait0();
            }
            __syncthreads();
            #pragma unroll
            for (int kh = 0; kh < 2; kh++) {
                uint32_t af[2][4], bq[4][4];
                #pragma unroll
                for (int mt = 0; mt < 2; mt++)
                    ldsm16x16(&u.s[cur].Xs[pm0 + mt*16][kh*16], SX1, lane, af[mt]);
                #pragma unroll
                for (int np = 0; np < 4; np++)
                    ldsm16x16(&u.s[cur].Wt[pn0 + np*16][kh*16], SX1, lane, bq[np]);
                #pragma unroll
                for (int mt = 0; mt < 2; mt++)
                    #pragma unroll
                    for (int nt = 0; nt < 8; nt++)
                        mma16816(cacc[mt][nt],
                                 af[mt][0], af[mt][1], af[mt][2], af[mt][3],
                                 bq[nt>>1][nt&1], bq[nt>>1][2 + (nt&1)]);
            }
            __syncthreads();
            xr[0]=xn[0]; xr[1]=xn[1]; xr[2]=xn[2]; xr[3]=xn[3];
        }

        // epilogue: phi + transposed fp16 store into kT/vT (aliases stages)
        #pragma unroll
        for (int mt = 0; mt < 2; mt++) {
            const int r0 = pm0 + mt*16 + g;
            #pragma unroll
            for (int nt = 0; nt < 8; nt++) {
                const int c = pn0 + nt*8 + tig*2;
                const float* cc = cacc[mt][nt];
                if (pni == 0) {
                    u.b.kT[c+0][r0]   = __float2half(phi_map(cc[0]));
                    u.b.kT[c+1][r0]   = __float2half(phi_map(cc[1]));
                    u.b.kT[c+0][r0+8] = __float2half(phi_map(cc[2]));
                    u.b.kT[c+1][r0+8] = __float2half(phi_map(cc[3]));
                } else {
                    const int e = c - 64;
                    u.b.vT[e+0][r0]   = __float2half(cc[0]);
                    u.b.vT[e+1][r0]   = __float2half(cc[1]);
                    u.b.vT[e+0][r0+8] = __float2half(cc[2]);
                    u.b.vT[e+1][r0+8] = __float2half(cc[3]);
                }
            }
        }
        __syncthreads();
        {   // Ksum distributed over 256 threads
            const int d = tid & 63, part = tid >> 6;
            float s = 0.0f;
            #pragma unroll
            for (int n = 0; n < 32; n++) s += __half2float(u.b.kT[d][part*32 + n]);
            ksum += s;
        }
        // KV += kT[64 x 128] @ vT^T
        #pragma unroll
        for (int ks = 0; ks < 8; ks++) {
            uint32_t af[2][4], bq[4];
            #pragma unroll
            for (int mt = 0; mt < 2; mt++)
                ldsm16x16(&u.b.kT[kd0 + mt*16][ks*16], SKT, lane, af[mt]);
            ldsm16x16(&u.b.vT[ke0][ks*16], SKT, lane, bq);
            #pragma unroll
            for (int mt = 0; mt < 2; mt++)
                #pragma unroll
                for (int nt = 0; nt < 2; nt++)
                    mma16816(kvacc[mt][nt],
                             af[mt][0], af[mt][1], af[mt][2], af[mt][3],
                             bq[nt], bq[2 + nt]);
        }
        __syncthreads();
    }
    // write partials
    #pragma unroll
    for (int mt = 0; mt < 2; mt++) {
        const int d = kd0 + mt*16 + g;
        #pragma unroll
        for (int nt = 0; nt < 2; nt++) {
            const int e = ke0 + nt*8 + tig*2;
            g_KV_part[chunk][bh][d  ][e  ] = kvacc[mt][nt][0];
            g_KV_part[chunk][bh][d  ][e+1] = kvacc[mt][nt][1];
            g_KV_part[chunk][bh][d+8][e  ] = kvacc[mt][nt][2];
            g_KV_part[chunk][bh][d+8][e+1] = kvacc[mt][nt][3];
        }
    }
    red[tid] = ksum;
    __syncthreads();
    if (tid < 64)
        g_Ksum_part[chunk][bh][tid] = red[tid] + red[tid+64] + red[tid+128] + red[tid+192];
}

// ===========================================================================
// K2: reduce partials
// ===========================================================================
__global__ __launch_bounds__(256)
void kv_reduce_kernel()
{
    const int idx = blockIdx.x * 256 + threadIdx.x;
    if (idx < NBH*HD*HD) {
        const int bh = idx >> 12, r = idx & 4095;
        float s = 0.0f;
        #pragma unroll
        for (int p = 0; p < KVCH; p++) s += (&g_KV_part[p][bh][0][0])[r];
        (&g_KV[bh][0][0])[r] = s;
    }
    if (idx < NBH*HD) {
        const int bh = idx >> 6, d = idx & 63;
        float s = 0.0f;
        #pragma unroll
        for (int p = 0; p < KVCH; p++) s += g_Ksum_part[p][bh][d];
        g_Ksum[bh][d] = s;
    }
}

// ===========================================================================
// K3: q projection as full 128x128-tile GEMM (2 heads/block) + per-head attn.
// Grid (4 col-tiles fastest, 256 token-blocks). 256 threads.
// ===========================================================================
#define SX3 40
#define SQ3 136   // qs stride: 272B rows, conflict-free ldmatrix
#define SKV 72

struct K3Stage { __half Xs[128][SX3]; __half Wt[128][SX3]; };   // 20480 B
struct K3B { __half qs[128][SQ3]; __half KVt[64][SKV];
             float kss[64]; float den[128]; };                  // 44800 B

__global__ __launch_bounds__(256, 1)
void q_attn_kernel(const float* __restrict__ x)
{
    __shared__ alignas(16) union { K3Stage s[2]; K3B b; } u;    // 44800 B

    const int cy = blockIdx.x;             // 0..3: q col-tile (heads 2cy, 2cy+1)
    const int brow = blockIdx.y;           // 0..255 token-block
    const int tid = threadIdx.x, lane = tid & 31, warp = tid >> 5;
    const int g = lane >> 2, tig = lane & 3;
    const int bb = brow >> 5;              // batch (128-token blocks never straddle)
    const int bh_base = bb*NH + cy*2;

    const int m0 = (warp >> 1) * 32;
    const int pni = warp & 1;
    const int n0w = pni * 64;

    const int srow = tid >> 1, sside = (tid & 1) * 16;
    const float* xrow = x + ((size_t)(brow*128 + srow))*CDIM + sside;
    const __half* wrow = g_WqkvT[cy*128 + srow];   // q section = rows 0..511

    // ---- Phase 1: q projection 128x128, K=512, 2-stage pipeline ----
    float cacc[2][8][4] = {};
    float4 xr[4], xn[4];
    xr[0] = *(const float4*)(xrow);      xr[1] = *(const float4*)(xrow + 4);
    xr[2] = *(const float4*)(xrow + 8);  xr[3] = *(const float4*)(xrow + 12);
    cp16(&u.s[0].Wt[srow][sside],     wrow + sside);
    cp16(&u.s[0].Wt[srow][sside + 8], wrow + sside + 8);
    cp_commit();

    for (int kc = 0; kc < 16; kc++) {
        const int cur = kc & 1;
        cvt_sts16(&u.s[cur].Xs[srow][sside], xr);
        if (kc < 15) {
            const float* nsrc = xrow + (kc+1)*32;
            xn[0] = *(const float4*)(nsrc);      xn[1] = *(const float4*)(nsrc + 4);
            xn[2] = *(const float4*)(nsrc + 8);  xn[3] = *(const float4*)(nsrc + 12);
            const __half* wsrc = wrow + (kc+1)*32 + sside;
            cp16(&u.s[cur^1].Wt[srow][sside],     wsrc);
            cp16(&u.s[cur^1].Wt[srow][sside + 8], wsrc + 8);
            cp_commit();
            cp_wait1();
        } else {
            cp_wait0();
        }
        __syncthreads();
        #pragma unroll
        for (int kh = 0; kh < 2; kh++) {
            uint32_t af[2][4], bq[4][4];
            #pragma unroll
            for (int mt = 0; mt < 2; mt++)
                ldsm16x16(&u.s[cur].Xs[m0 + mt*16][kh*16], SX3, lane, af[mt]);
            #pragma unroll
            for (int np = 0; np < 4; np++)
                ldsm16x16(&u.s[cur].Wt[n0w + np*16][kh*16], SX3, lane, bq[np]);
            #pragma unroll
            for (int mt = 0; mt < 2; mt++)
                #pragma unroll
                for (int nt = 0; nt < 8; nt++)
                    mma16816(cacc[mt][nt],
                             af[mt][0], af[mt][1], af[mt][2], af[mt][3],
                             bq[nt>>1][nt&1], bq[nt>>1][2 + (nt&1)]);
        }
        __syncthreads();
        xr[0]=xn[0]; xr[1]=xn[1]; xr[2]=xn[2]; xr[3]=xn[3];
    }

    // ---- Phase 2: phi -> qs (all 128 cols), frees cacc ----
    #pragma unroll
    for (int mt = 0; mt < 2; mt++) {
        const int r0 = m0 + mt*16 + g;
        #pragma unroll
        for (int nt = 0; nt < 8; nt++) {
            const int c = n0w + nt*8 + tig*2;
            const float* cc = cacc[mt][nt];
            u.b.qs[r0  ][c  ] = __float2half(phi_map(cc[0]));
            u.b.qs[r0  ][c+1] = __float2half(phi_map(cc[1]));
            u.b.qs[r0+8][c  ] = __float2half(phi_map(cc[2]));
            u.b.qs[r0+8][c+1] = __float2half(phi_map(cc[3]));
        }
    }

    // ---- Phase 3: per-head attn ----
    #pragma unroll
    for (int hh = 0; hh < 2; hh++) {
        const int bh = bh_base + hh;
        const int h  = cy*2 + hh;
        // stage KVt (transposed) + kss for this head
        if (hh == 0) __syncthreads();     // qs visible before any reads
        #pragma unroll
        for (int i = 0; i < 16; i++) {
            const int lin = tid*16 + i;
            const int d = lin >> 6, e = lin & 63;
            u.b.KVt[e][d] = __float2half(g_KV[bh][d][e]);
        }
        if (tid < 64) u.b.kss[tid] = g_Ksum[bh][tid];
        __syncthreads();
        if (tid < 128) {
            float s = 0.0f;
            #pragma unroll
            for (int d = 0; d < 64; d++)
                s += __half2float(u.b.qs[tid][hh*64 + d]) * u.b.kss[d];
            u.b.den[tid] = s;
        }
        __syncthreads();
        // attn mma: M=128, N=64, K=64; warp grid 4(m) x 2(n)
        float oacc[2][4][4] = {};
        #pragma unroll
        for (int ks = 0; ks < 4; ks++) {
            uint32_t af[2][4], bq[2][4];
            #pragma unroll
            for (int mt = 0; mt < 2; mt++)
                ldsm16x16(&u.b.qs[m0 + mt*16][hh*64 + ks*16], SQ3, lane, af[mt]);
            #pragma unroll
            for (int np = 0; np < 2; np++)
                ldsm16x16(&u.b.KVt[pni*32 + np*16][ks*16], SKV, lane, bq[np]);
            #pragma unroll
            for (int mt = 0; mt < 2; mt++)
                #pragma unroll
                for (int nt = 0; nt < 4; nt++)
                    mma16816(oacc[mt][nt],
                             af[mt][0], af[mt][1], af[mt][2], af[mt][3],
                             bq[nt>>1][nt&1], bq[nt>>1][2 + (nt&1)]);
        }
        // normalize + fp16 store
        #pragma unroll
        for (int mt = 0; mt < 2; mt++) {
            const int r0 = m0 + mt*16 + g;
            const float inv0 = 1.0f / (u.b.den[r0]   + 1e-6f);
            const float inv1 = 1.0f / (u.b.den[r0+8] + 1e-6f);
            const size_t row0 = (size_t)(brow*128 + r0);
            #pragma unroll
            for (int nt = 0; nt < 4; nt++) {
                const int c = pni*32 + nt*8 + tig*2;
                const float* cc = oacc[mt][nt];
                __half2* d0p = (__half2*)&g_attnh[row0*CDIM + h*64 + c];
                __half2* d1p = (__half2*)&g_attnh[(row0+8)*CDIM + h*64 + c];
                *d0p = __floats2half2_rn(cc[0]*inv0, cc[1]*inv0);
                *d1p = __floats2half2_rn(cc[2]*inv1, cc[3]*inv1);
            }
        }
        if (hh == 0) __syncthreads();     // before restaging KVt/kss/den
    }
}

// ===========================================================================
// K4: out = attnh(fp16) @ W_out + bias -- cp.async double-buffered.
// Grid (4 col-tiles fastest, 256 row-tiles) for L2 attn reuse.
// ===========================================================================
#define SX4 40

struct K4Stage { __half Xs[128][SX4]; __half Wt[128][SX4]; };   // 20480 B

__global__ __launch_bounds__(256, 1)
void out_proj_kernel(const float* __restrict__ bias,
                     float* __restrict__ Cout)
{
    __shared__ alignas(16) K4Stage s[2];                         // 40960 B

    const int tid = threadIdx.x, lane = tid & 31, warp = tid >> 5;
    const int g = lane >> 2, tig = lane & 3;
    const int bcol = blockIdx.x, brow = blockIdx.y;
    const int m0 = (warp >> 1) * 32;
    const int n0w = (warp & 1) * 64;
    const int srow = tid >> 1, sside = (tid & 1) * 16;

    const __half* arow = g_attnh + (size_t)(brow*128 + srow)*CDIM + sside;
    const __half* wrow = &g_WoutT[bcol*128 + srow][sside];

    cp16(&s[0].Xs[srow][sside],     arow);
    cp16(&s[0].Xs[srow][sside + 8], arow + 8);
    cp16(&s[0].Wt[srow][sside],     wrow);
    cp16(&s[0].Wt[srow][sside + 8], wrow + 8);
    cp_commit();

    float cacc[2][8][4] = {};
    for (int kc = 0; kc < 16; kc++) {
        const int cur = kc & 1;
        if (kc < 15) {
            const __half* an = arow + (kc+1)*32;
            const __half* wn = wrow + (kc+1)*32;
            cp16(&s[cur^1].Xs[srow][sside],     an);
            cp16(&s[cur^1].Xs[srow][sside + 8], an + 8);
            cp16(&s[cur^1].Wt[srow][sside],     wn);
            cp16(&s[cur^1].Wt[srow][sside + 8], wn + 8);
            cp_commit();
            cp_wait1();
        } else {
            cp_wait0();
        }
        __syncthreads();
        #pragma unroll
        for (int kh = 0; kh < 2; kh++) {
            uint32_t af[2][4], bq[4][4];
            #pragma unroll
            for (int mt = 0; mt < 2; mt++)
                ldsm16x16(&s[cur].Xs[m0 + mt*16][kh*16], SX4, lane, af[mt]);
            #pragma unroll
            for (int np = 0; np < 4; np++)
                ldsm16x16(&s[cur].Wt[n0w + np*16][kh*16], SX4, lane, bq[np]);
            #pragma unroll
            for (int mt = 0; mt < 2; mt++)
                #pragma unroll
                for (int nt = 0; nt < 8; nt++)
                    mma16816(cacc[mt][nt],
                             af[mt][0], af[mt][1], af[mt][2], af[mt][3],
                             bq[nt>>1][nt&1], bq[nt>>1][2 + (nt&1)]);
        }
        __syncthreads();
    }
    #pragma unroll
    for (int mt = 0; mt < 2; mt++) {
        const int r0 = brow*128 + m0 + mt*16 + g;
        #pragma unroll
        for (int nt = 0; nt < 8; nt++) {
            const int c = bcol*128 + n0w + nt*8 + tig*2;
            const float2 bv = *(const float2*)&bias[c];
            const float* cc = cacc[mt][nt];
            float2 o0 = { cc[0] + bv.x, cc[1] + bv.y };
            float2 o1 = { cc[2] + bv.x, cc[3] + bv.y };
            *(float2*)&Cout[(size_t)r0*CDIM + c]     = o0;
            *(float2*)&Cout[(size_t)(r0+8)*CDIM + c] = o1;
        }
    }
}

// ===========================================================================
extern "C" void kernel_launch(void* const* d_in, const int* in_sizes, int n_in,
                              void* d_out, int out_size)
{
    const float* x     = (const float*)d_in[0];
    const float* W_qkv = (const float*)d_in[1];
    const float* W_out = (const float*)d_in[2];
    const float* b_out = (const float*)d_in[3];
    float* out = (float*)d_out;

    {   __half* wqkvT = nullptr; cudaGetSymbolAddress((void**)&wqkvT, g_WqkvT);
        __half* woutT = nullptr; cudaGetSymbolAddress((void**)&woutT, g_WoutT);
        transpose_w_kernel<<<dim3(3*CDIM/32, CDIM/32), 256>>>(W_qkv, wqkvT, CDIM, 3*CDIM);
        transpose_w_kernel<<<dim3(CDIM/32, CDIM/32),   256>>>(W_out, woutT, CDIM, CDIM);
    }
    {   dim3 grid(NBH, KVCH);                 // 64 x 8
        kv_build_kernel<<<grid, 256>>>(x); }
    kv_reduce_kernel<<<(NBH*HD*HD + 255)/256, 256>>>();
    {   dim3 grid(4, MROWS/128);              // col-tile fastest -> L2 x reuse
        q_attn_kernel<<<grid, 256>>>(x); }
    {   dim3 grid(CDIM/128, MROWS/128);       // col-tile fastest -> L2 attn reuse
        out_proj_kernel<<<grid, 256>>>(b_out, out); }
}

// round 12
// speedup vs baseline: 9.7709x; 1.2163x over previous
#include <cuda_runtime.h>
#include <cuda_fp16.h>
#include <cstdint>
#include <math.h>

#define BB   8
#define SEQ  4096
#define CDIM 512
#define NH   8
#define HD   64
#define MROWS (BB*SEQ)   // 32768
#define NBH  (BB*NH)     // 64
#define KVCH 8

// ---------------- static device scratch (~44 MB, known-safe) ---------------
__device__ float  g_KV_part[KVCH][NBH][HD][HD];
__device__ float  g_Ksum_part[KVCH][NBH][HD];
__device__ float  g_KV[NBH][HD][HD];
__device__ float  g_Ksum[NBH][HD];
__device__ __half g_attnh[(size_t)MROWS*CDIM];    // 32 MB
__device__ __half g_WqkvT[3*CDIM][CDIM];          // 1.5 MB  [out_col][k]
__device__ __half g_WoutT[CDIM][CDIM];            // 0.5 MB  [out_col][k]

__device__ __forceinline__ float phi_map(float x) {
    return x > 0.0f ? x + 1.0f : __expf(x);
}
__device__ __forceinline__ uint32_t f2h2(float a, float b) {
    __half2 h = __floats2half2_rn(a, b);
    return *reinterpret_cast<uint32_t*>(&h);
}

// ---- cp.async helpers ------------------------------------------------------
__device__ __forceinline__ void cp16(void* dst, const void* src) {
    uint32_t d = (uint32_t)__cvta_generic_to_shared(dst);
    asm volatile("cp.async.cg.shared.global [%0], [%1], 16;" :: "r"(d), "l"(src));
}
__device__ __forceinline__ void cp_commit() { asm volatile("cp.async.commit_group;" ::: "memory"); }
__device__ __forceinline__ void cp_wait0()  { asm volatile("cp.async.wait_group 0;" ::: "memory"); }
__device__ __forceinline__ void cp_wait1()  { asm volatile("cp.async.wait_group 1;" ::: "memory"); }

// ---- mma.sync m16n8k16 fp16 -> fp32 ---------------------------------------
__device__ __forceinline__ void mma16816(float* c,
    uint32_t a0, uint32_t a1, uint32_t a2, uint32_t a3,
    uint32_t b0, uint32_t b1)
{
    asm volatile(
        "mma.sync.aligned.m16n8k16.row.col.f32.f16.f16.f32 "
        "{%0,%1,%2,%3},{%4,%5,%6,%7},{%8,%9},{%0,%1,%2,%3};"
        : "+f"(c[0]), "+f"(c[1]), "+f"(c[2]), "+f"(c[3])
        : "r"(a0), "r"(a1), "r"(a2), "r"(a3), "r"(b0), "r"(b1));
}

// ldmatrix x4 of a 16x16 fp16 tile at (row0, k0), row stride S halves.
__device__ __forceinline__ void ldsm16x16(const __half* tile, int S, int lane, uint32_t* r) {
    const int t = lane >> 3, j = lane & 7;
    const __half* addr = tile + (size_t)(((t & 1) << 3) + j) * S + ((t >> 1) << 3);
    uint32_t a = (uint32_t)__cvta_generic_to_shared(addr);
    asm volatile("ldmatrix.sync.aligned.m8n8.x4.shared.b16 {%0,%1,%2,%3}, [%4];"
                 : "=r"(r[0]), "=r"(r[1]), "=r"(r[2]), "=r"(r[3]) : "r"(a));
}

// pack 16 fp32 (4 float4) -> 2 uint4 of halves, store to smem row
__device__ __forceinline__ void cvt_sts16(__half* dst, const float4* v) {
    uint4 w0, w1;
    w0.x = f2h2(v[0].x, v[0].y); w0.y = f2h2(v[0].z, v[0].w);
    w0.z = f2h2(v[1].x, v[1].y); w0.w = f2h2(v[1].z, v[1].w);
    w1.x = f2h2(v[2].x, v[2].y); w1.y = f2h2(v[2].z, v[2].w);
    w1.z = f2h2(v[3].x, v[3].y); w1.w = f2h2(v[3].z, v[3].w);
    *(uint4*)(dst)     = w0;
    *(uint4*)(dst + 8) = w1;
}

// ===========================================================================
// K0: W[R][C] fp32  ->  WT[C][R] fp16
// ===========================================================================
__global__ __launch_bounds__(256)
void transpose_w_kernel(const float* __restrict__ W, __half* __restrict__ WT,
                        int R, int C)
{
    __shared__ __half ts[32][33];
    const int tid = threadIdx.x;
    const int r = tid >> 3, c4 = (tid & 7) * 4;
    const float* src = W + (size_t)(blockIdx.y*32 + r)*C + blockIdx.x*32 + c4;
    const float4 v = *(const float4*)src;
    ts[c4+0][r] = __float2half(v.x);
    ts[c4+1][r] = __float2half(v.y);
    ts[c4+2][r] = __float2half(v.z);
    ts[c4+3][r] = __float2half(v.w);
    __syncthreads();
    __half* dst = WT + (size_t)(blockIdx.x*32 + r)*R + blockIdx.y*32 + c4;
    dst[0] = ts[r][c4+0]; dst[1] = ts[r][c4+1];
    dst[2] = ts[r][c4+2]; dst[3] = ts[r][c4+3];
}

// ===========================================================================
// K1: fused k/v projection (mma, pipelined) + KV/Ksum accumulation (mma).
// Block = (bh, chunk of 512 tokens), 256 threads (8 warps), 2 blocks/SM.
// ===========================================================================
#define SX1 40
#define SKT 136

struct K1Stage { __half Xs[128][SX1]; __half Wt[128][SX1]; };   // 20480 B
struct K1B     { __half kT[64][SKT];  __half vT[64][SKT];  };   // 34816 B

__global__ __launch_bounds__(256, 2)
void kv_build_kernel(const float* __restrict__ x)
{
    __shared__ alignas(16) union { K1Stage s[2]; K1B b; } u;    // 40960 B
    __shared__ float red[256];

    const int bh = blockIdx.x, chunk = blockIdx.y;
    const int tid = threadIdx.x, lane = tid & 31, warp = tid >> 5;
    const int g = lane >> 2, tig = lane & 3;
    const int b = bh >> 3, h = bh & 7;

    const int pm0 = (warp >> 1) * 32;      // proj warp grid 4x2
    const int pni = warp & 1;
    const int pn0 = pni * 64;
    const int kd0 = (warp >> 2) * 32;      // KV warp grid 2x4
    const int ke0 = (warp & 3) * 16;

    float kvacc[2][2][4] = {};
    float ksum = 0.0f;

    const float* xb = x + ((size_t)b*SEQ + chunk*512) * CDIM;
    const int srow = tid >> 1, sside = (tid & 1) * 16;
    const int wgn = (srow < 64) ? (512 + h*64 + srow) : (1024 + h*64 + (srow - 64));
    const __half* wrow = g_WqkvT[wgn];

    for (int st = 0; st < 4; st++) {
        float cacc[2][8][4] = {};
        const float* xrow = xb + (size_t)(st*128 + srow)*CDIM + sside;

        float4 xr[4], xn[4];
        xr[0] = *(const float4*)(xrow);      xr[1] = *(const float4*)(xrow + 4);
        xr[2] = *(const float4*)(xrow + 8);  xr[3] = *(const float4*)(xrow + 12);
        cp16(&u.s[0].Wt[srow][sside],     wrow + sside);
        cp16(&u.s[0].Wt[srow][sside + 8], wrow + sside + 8);
        cp_commit();

        for (int kc = 0; kc < 16; kc++) {
            const int cur = kc & 1;
            cvt_sts16(&u.s[cur].Xs[srow][sside], xr);
            if (kc < 15) {
                const float* nsrc = xrow + (kc+1)*32;
                xn[0] = *(const float4*)(nsrc);      xn[1] = *(const float4*)(nsrc + 4);
                xn[2] = *(const float4*)(nsrc + 8);  xn[3] = *(const float4*)(nsrc + 12);
                const __half* wsrc = wrow + (kc+1)*32 + sside;
                cp16(&u.s[cur^1].Wt[srow][sside],     wsrc);
                cp16(&u.s[cur^1].Wt[srow][sside + 8], wsrc + 8);
                cp_commit();
                cp_wait1();
            } else {
                cp_wait0();
            }
            __syncthreads();
            #pragma unroll
            for (int kh = 0; kh < 2; kh++) {
                uint32_t af[2][4], bq[4][4];
                #pragma unroll
                for (int mt = 0; mt < 2; mt++)
                    ldsm16x16(&u.s[cur].Xs[pm0 + mt*16][kh*16], SX1, lane, af[mt]);
                #pragma unroll
                for (int np = 0; np < 4; np++)
                    ldsm16x16(&u.s[cur].Wt[pn0 + np*16][kh*16], SX1, lane, bq[np]);
                #pragma unroll
                for (int mt = 0; mt < 2; mt++)
                    #pragma unroll
                    for (int nt = 0; nt < 8; nt++)
                        mma16816(cacc[mt][nt],
                                 af[mt][0], af[mt][1], af[mt][2], af[mt][3],
                                 bq[nt>>1][nt&1], bq[nt>>1][2 + (nt&1)]);
            }
            __syncthreads();
            xr[0]=xn[0]; xr[1]=xn[1]; xr[2]=xn[2]; xr[3]=xn[3];
        }

        // epilogue: phi + transposed fp16 store into kT/vT (aliases stages)
        #pragma unroll
        for (int mt = 0; mt < 2; mt++) {
            const int r0 = pm0 + mt*16 + g;
            #pragma unroll
            for (int nt = 0; nt < 8; nt++) {
                const int c = pn0 + nt*8 + tig*2;
                const float* cc = cacc[mt][nt];
                if (pni == 0) {
                    u.b.kT[c+0][r0]   = __float2half(phi_map(cc[0]));
                    u.b.kT[c+1][r0]   = __float2half(phi_map(cc[1]));
                    u.b.kT[c+0][r0+8] = __float2half(phi_map(cc[2]));
                    u.b.kT[c+1][r0+8] = __float2half(phi_map(cc[3]));
                } else {
                    const int e = c - 64;
                    u.b.vT[e+0][r0]   = __float2half(cc[0]);
                    u.b.vT[e+1][r0]   = __float2half(cc[1]);
                    u.b.vT[e+0][r0+8] = __float2half(cc[2]);
                    u.b.vT[e+1][r0+8] = __float2half(cc[3]);
                }
            }
        }
        __syncthreads();
        {   // Ksum distributed over 256 threads
            const int d = tid & 63, part = tid >> 6;
            float s = 0.0f;
            #pragma unroll
            for (int n = 0; n < 32; n++) s += __half2float(u.b.kT[d][part*32 + n]);
            ksum += s;
        }
        // KV += kT[64 x 128] @ vT^T
        #pragma unroll
        for (int ks = 0; ks < 8; ks++) {
            uint32_t af[2][4], bq[4];
            #pragma unroll
            for (int mt = 0; mt < 2; mt++)
                ldsm16x16(&u.b.kT[kd0 + mt*16][ks*16], SKT, lane, af[mt]);
            ldsm16x16(&u.b.vT[ke0][ks*16], SKT, lane, bq);
            #pragma unroll
            for (int mt = 0; mt < 2; mt++)
                #pragma unroll
                for (int nt = 0; nt < 2; nt++)
                    mma16816(kvacc[mt][nt],
                             af[mt][0], af[mt][1], af[mt][2], af[mt][3],
                             bq[nt], bq[2 + nt]);
        }
        __syncthreads();
    }
    // write partials
    #pragma unroll
    for (int mt = 0; mt < 2; mt++) {
        const int d = kd0 + mt*16 + g;
        #pragma unroll
        for (int nt = 0; nt < 2; nt++) {
            const int e = ke0 + nt*8 + tig*2;
            g_KV_part[chunk][bh][d  ][e  ] = kvacc[mt][nt][0];
            g_KV_part[chunk][bh][d  ][e+1] = kvacc[mt][nt][1];
            g_KV_part[chunk][bh][d+8][e  ] = kvacc[mt][nt][2];
            g_KV_part[chunk][bh][d+8][e+1] = kvacc[mt][nt][3];
        }
    }
    red[tid] = ksum;
    __syncthreads();
    if (tid < 64)
        g_Ksum_part[chunk][bh][tid] = red[tid] + red[tid+64] + red[tid+128] + red[tid+192];
}

// ===========================================================================
// K2: reduce partials
// ===========================================================================
__global__ __launch_bounds__(256)
void kv_reduce_kernel()
{
    const int idx = blockIdx.x * 256 + threadIdx.x;
    if (idx < NBH*HD*HD) {
        const int bh = idx >> 12, r = idx & 4095;
        float s = 0.0f;
        #pragma unroll
        for (int p = 0; p < KVCH; p++) s += (&g_KV_part[p][bh][0][0])[r];
        (&g_KV[bh][0][0])[r] = s;
    }
    if (idx < NBH*HD) {
        const int bh = idx >> 6, d = idx & 63;
        float s = 0.0f;
        #pragma unroll
        for (int p = 0; p < KVCH; p++) s += g_Ksum_part[p][bh][d];
        g_Ksum[bh][d] = s;
    }
}

// ===========================================================================
// K3: q projection as full 128x128-tile GEMM (2 heads/block) + per-head attn.
// Grid (4 col-tiles fastest, 256 token-blocks). 256 threads, 2 blocks/SM.
// ===========================================================================
#define SX3 40
#define SQ3 136   // qs stride: 272B rows, conflict-free ldmatrix
#define SKV 72

struct K3Stage { __half Xs[128][SX3]; __half Wt[128][SX3]; };   // 20480 B
struct K3B { __half qs[128][SQ3]; __half KVt[64][SKV];
             float kss[64]; float den[128]; };                  // 44800 B

__global__ __launch_bounds__(256, 2)
void q_attn_kernel(const float* __restrict__ x)
{
    __shared__ alignas(16) union { K3Stage s[2]; K3B b; } u;    // 44800 B

    const int cy = blockIdx.x;             // 0..3: q col-tile (heads 2cy, 2cy+1)
    const int brow = blockIdx.y;           // 0..255 token-block
    const int tid = threadIdx.x, lane = tid & 31, warp = tid >> 5;
    const int g = lane >> 2, tig = lane & 3;
    const int bb = brow >> 5;              // batch (128-token blocks never straddle)
    const int bh_base = bb*NH + cy*2;

    const int m0 = (warp >> 1) * 32;
    const int pni = warp & 1;
    const int n0w = pni * 64;

    const int srow = tid >> 1, sside = (tid & 1) * 16;
    const float* xrow = x + ((size_t)(brow*128 + srow))*CDIM + sside;
    const __half* wrow = g_WqkvT[cy*128 + srow];   // q section = rows 0..511

    // ---- Phase 1: q projection 128x128, K=512, 2-stage pipeline ----
    float cacc[2][8][4] = {};
    float4 xr[4], xn[4];
    xr[0] = *(const float4*)(xrow);      xr[1] = *(const float4*)(xrow + 4);
    xr[2] = *(const float4*)(xrow + 8);  xr[3] = *(const float4*)(xrow + 12);
    cp16(&u.s[0].Wt[srow][sside],     wrow + sside);
    cp16(&u.s[0].Wt[srow][sside + 8], wrow + sside + 8);
    cp_commit();

    for (int kc = 0; kc < 16; kc++) {
        const int cur = kc & 1;
        cvt_sts16(&u.s[cur].Xs[srow][sside], xr);
        if (kc < 15) {
            const float* nsrc = xrow + (kc+1)*32;
            xn[0] = *(const float4*)(nsrc);      xn[1] = *(const float4*)(nsrc + 4);
            xn[2] = *(const float4*)(nsrc + 8);  xn[3] = *(const float4*)(nsrc + 12);
            const __half* wsrc = wrow + (kc+1)*32 + sside;
            cp16(&u.s[cur^1].Wt[srow][sside],     wsrc);
            cp16(&u.s[cur^1].Wt[srow][sside + 8], wsrc + 8);
            cp_commit();
            cp_wait1();
        } else {
            cp_wait0();
        }
        __syncthreads();
        #pragma unroll
        for (int kh = 0; kh < 2; kh++) {
            uint32_t af[2][4], bq[4][4];
            #pragma unroll
            for (int mt = 0; mt < 2; mt++)
                ldsm16x16(&u.s[cur].Xs[m0 + mt*16][kh*16], SX3, lane, af[mt]);
            #pragma unroll
            for (int np = 0; np < 4; np++)
                ldsm16x16(&u.s[cur].Wt[n0w + np*16][kh*16], SX3, lane, bq[np]);
            #pragma unroll
            for (int mt = 0; mt < 2; mt++)
                #pragma unroll
                for (int nt = 0; nt < 8; nt++)
                    mma16816(cacc[mt][nt],
                             af[mt][0], af[mt][1], af[mt][2], af[mt][3],
                             bq[nt>>1][nt&1], bq[nt>>1][2 + (nt&1)]);
        }
        __syncthreads();
        xr[0]=xn[0]; xr[1]=xn[1]; xr[2]=xn[2]; xr[3]=xn[3];
    }

    // ---- Phase 2: phi -> qs (all 128 cols), frees cacc ----
    #pragma unroll
    for (int mt = 0; mt < 2; mt++) {
        const int r0 = m0 + mt*16 + g;
        #pragma unroll
        for (int nt = 0; nt < 8; nt++) {
            const int c = n0w + nt*8 + tig*2;
            const float* cc = cacc[mt][nt];
            u.b.qs[r0  ][c  ] = __float2half(phi_map(cc[0]));
            u.b.qs[r0  ][c+1] = __float2half(phi_map(cc[1]));
            u.b.qs[r0+8][c  ] = __float2half(phi_map(cc[2]));
            u.b.qs[r0+8][c+1] = __float2half(phi_map(cc[3]));
        }
    }

    // ---- Phase 3: per-head attn ----
    #pragma unroll
    for (int hh = 0; hh < 2; hh++) {
        const int bh = bh_base + hh;
        const int h  = cy*2 + hh;
        // stage KVt (transposed) + kss for this head
        if (hh == 0) __syncthreads();     // qs visible before any reads
        #pragma unroll
        for (int i = 0; i < 16; i++) {
            const int lin = tid*16 + i;
            const int d = lin >> 6, e = lin & 63;
            u.b.KVt[e][d] = __float2half(g_KV[bh][d][e]);
        }
        if (tid < 64) u.b.kss[tid] = g_Ksum[bh][tid];
        __syncthreads();
        if (tid < 128) {
            float s = 0.0f;
            #pragma unroll
            for (int d = 0; d < 64; d++)
                s += __half2float(u.b.qs[tid][hh*64 + d]) * u.b.kss[d];
            u.b.den[tid] = s;
        }
        __syncthreads();
        // attn mma: M=128, N=64, K=64; warp grid 4(m) x 2(n)
        float oacc[2][4][4] = {};
        #pragma unroll
        for (int ks = 0; ks < 4; ks++) {
            uint32_t af[2][4], bq[2][4];
            #pragma unroll
            for (int mt = 0; mt < 2; mt++)
                ldsm16x16(&u.b.qs[m0 + mt*16][hh*64 + ks*16], SQ3, lane, af[mt]);
            #pragma unroll
            for (int np = 0; np < 2; np++)
                ldsm16x16(&u.b.KVt[pni*32 + np*16][ks*16], SKV, lane, bq[np]);
            #pragma unroll
            for (int mt = 0; mt < 2; mt++)
                #pragma unroll
                for (int nt = 0; nt < 4; nt++)
                    mma16816(oacc[mt][nt],
                             af[mt][0], af[mt][1], af[mt][2], af[mt][3],
                             bq[nt>>1][nt&1], bq[nt>>1][2 + (nt&1)]);
        }
        // normalize + fp16 store
        #pragma unroll
        for (int mt = 0; mt < 2; mt++) {
            const int r0 = m0 + mt*16 + g;
            const float inv0 = 1.0f / (u.b.den[r0]   + 1e-6f);
            const float inv1 = 1.0f / (u.b.den[r0+8] + 1e-6f);
            const size_t row0 = (size_t)(brow*128 + r0);
            #pragma unroll
            for (int nt = 0; nt < 4; nt++) {
                const int c = pni*32 + nt*8 + tig*2;
                const float* cc = oacc[mt][nt];
                __half2* d0p = (__half2*)&g_attnh[row0*CDIM + h*64 + c];
                __half2* d1p = (__half2*)&g_attnh[(row0+8)*CDIM + h*64 + c];
                *d0p = __floats2half2_rn(cc[0]*inv0, cc[1]*inv0);
                *d1p = __floats2half2_rn(cc[2]*inv1, cc[3]*inv1);
            }
        }
        if (hh == 0) __syncthreads();     // before restaging KVt/kss/den
    }
}

// ===========================================================================
// K4: out = attnh(fp16) @ W_out + bias -- cp.async double-buffered.
// Grid (4 col-tiles fastest, 256 row-tiles). 2 blocks/SM.
// ===========================================================================
#define SX4 40

struct K4Stage { __half Xs[128][SX4]; __half Wt[128][SX4]; };   // 20480 B

__global__ __launch_bounds__(256, 2)
void out_proj_kernel(const float* __restrict__ bias,
                     float* __restrict__ Cout)
{
    __shared__ alignas(16) K4Stage s[2];                         // 40960 B

    const int tid = threadIdx.x, lane = tid & 31, warp = tid >> 5;
    const int g = lane >> 2, tig = lane & 3;
    const int bcol = blockIdx.x, brow = blockIdx.y;
    const int m0 = (warp >> 1) * 32;
    const int n0w = (warp & 1) * 64;
    const int srow = tid >> 1, sside = (tid & 1) * 16;

    const __half* arow = g_attnh + (size_t)(brow*128 + srow)*CDIM + sside;
    const __half* wrow = &g_WoutT[bcol*128 + srow][sside];

    cp16(&s[0].Xs[srow][sside],     arow);
    cp16(&s[0].Xs[srow][sside + 8], arow + 8);
    cp16(&s[0].Wt[srow][sside],     wrow);
    cp16(&s[0].Wt[srow][sside + 8], wrow + 8);
    cp_commit();

    float cacc[2][8][4] = {};
    for (int kc = 0; kc < 16; kc++) {
        const int cur = kc & 1;
        if (kc < 15) {
            const __half* an = arow + (kc+1)*32;
            const __half* wn = wrow + (kc+1)*32;
            cp16(&s[cur^1].Xs[srow][sside],     an);
            cp16(&s[cur^1].Xs[srow][sside + 8], an + 8);
            cp16(&s[cur^1].Wt[srow][sside],     wn);
            cp16(&s[cur^1].Wt[srow][sside + 8], wn + 8);
            cp_commit();
            cp_wait1();
        } else {
            cp_wait0();
        }
        __syncthreads();
        #pragma unroll
        for (int kh = 0; kh < 2; kh++) {
            uint32_t af[2][4], bq[4][4];
            #pragma unroll
            for (int mt = 0; mt < 2; mt++)
                ldsm16x16(&s[cur].Xs[m0 + mt*16][kh*16], SX4, lane, af[mt]);
            #pragma unroll
            for (int np = 0; np < 4; np++)
                ldsm16x16(&s[cur].Wt[n0w + np*16][kh*16], SX4, lane, bq[np]);
            #pragma unroll
            for (int mt = 0; mt < 2; mt++)
                #pragma unroll
                for (int nt = 0; nt < 8; nt++)
                    mma16816(cacc[mt][nt],
                             af[mt][0], af[mt][1], af[mt][2], af[mt][3],
                             bq[nt>>1][nt&1], bq[nt>>1][2 + (nt&1)]);
        }
        __syncthreads();
    }
    #pragma unroll
    for (int mt = 0; mt < 2; mt++) {
        const int r0 = brow*128 + m0 + mt*16 + g;
        #pragma unroll
        for (int nt = 0; nt < 8; nt++) {
            const int c = bcol*128 + n0w + nt*8 + tig*2;
            const float2 bv = *(const float2*)&bias[c];
            const float* cc = cacc[mt][nt];
            float2 o0 = { cc[0] + bv.x, cc[1] + bv.y };
            float2 o1 = { cc[2] + bv.x, cc[3] + bv.y };
            *(float2*)&Cout[(size_t)r0*CDIM + c]     = o0;
            *(float2*)&Cout[(size_t)(r0+8)*CDIM + c] = o1;
        }
    }
}

// ===========================================================================
extern "C" void kernel_launch(void* const* d_in, const int* in_sizes, int n_in,
                              void* d_out, int out_size)
{
    const float* x     = (const float*)d_in[0];
    const float* W_qkv = (const float*)d_in[1];
    const float* W_out = (const float*)d_in[2];
    const float* b_out = (const float*)d_in[3];
    float* out = (float*)d_out;

    {   __half* wqkvT = nullptr; cudaGetSymbolAddress((void**)&wqkvT, g_WqkvT);
        __half* woutT = nullptr; cudaGetSymbolAddress((void**)&woutT, g_WoutT);
        transpose_w_kernel<<<dim3(3*CDIM/32, CDIM/32), 256>>>(W_qkv, wqkvT, CDIM, 3*CDIM);
        transpose_w_kernel<<<dim3(CDIM/32, CDIM/32),   256>>>(W_out, woutT, CDIM, CDIM);
    }
    {   dim3 grid(NBH, KVCH);                 // 64 x 8
        kv_build_kernel<<<grid, 256>>>(x); }
    kv_reduce_kernel<<<(NBH*HD*HD + 255)/256, 256>>>();
    {   dim3 grid(4, MROWS/128);              // col-tile fastest -> L2 x reuse
        q_attn_kernel<<<grid, 256>>>(x); }
    {   dim3 grid(CDIM/128, MROWS/128);       // col-tile fastest -> L2 attn reuse
        out_proj_kernel<<<grid, 256>>>(b_out, out); }
}

// round 15
// speedup vs baseline: 10.0580x; 1.0294x over previous
#include <cuda_runtime.h>
#include <cuda_fp16.h>
#include <cstdint>
#include <math.h>

#define BB   8
#define SEQ  4096
#define CDIM 512
#define NH   8
#define HD   64
#define MROWS (BB*SEQ)   // 32768
#define NBH  (BB*NH)     // 64
#define KVCH 8

// ---------------- static device scratch (~44 MB, known-safe) ---------------
__device__ float  g_KV_part[KVCH][NBH][HD][HD];
__device__ float  g_Ksum_part[KVCH][NBH][HD];
__device__ float  g_KV[NBH][HD][HD];
__device__ float  g_Ksum[NBH][HD];
__device__ __half g_attnh[(size_t)MROWS*CDIM];    // 32 MB
__device__ __half g_WqkvT[3*CDIM][CDIM];          // 1.5 MB  [out_col][k]
__device__ __half g_WoutT[CDIM][CDIM];            // 0.5 MB  [out_col][k]

__device__ __forceinline__ float phi_map(float x) {
    return x > 0.0f ? x + 1.0f : __expf(x);
}
__device__ __forceinline__ uint32_t f2h2(float a, float b) {
    __half2 h = __floats2half2_rn(a, b);
    return *reinterpret_cast<uint32_t*>(&h);
}

// ---- cp.async helpers ------------------------------------------------------
__device__ __forceinline__ void cp16(void* dst, const void* src) {
    uint32_t d = (uint32_t)__cvta_generic_to_shared(dst);
    asm volatile("cp.async.cg.shared.global [%0], [%1], 16;" :: "r"(d), "l"(src));
}
__device__ __forceinline__ void cp_commit() { asm volatile("cp.async.commit_group;" ::: "memory"); }
__device__ __forceinline__ void cp_wait0()  { asm volatile("cp.async.wait_group 0;" ::: "memory"); }
__device__ __forceinline__ void cp_wait1()  { asm volatile("cp.async.wait_group 1;" ::: "memory"); }

// ---- mma.sync m16n8k16 fp16 -> fp32 ---------------------------------------
__device__ __forceinline__ void mma16816(float* c,
    uint32_t a0, uint32_t a1, uint32_t a2, uint32_t a3,
    uint32_t b0, uint32_t b1)
{
    asm volatile(
        "mma.sync.aligned.m16n8k16.row.col.f32.f16.f16.f32 "
        "{%0,%1,%2,%3},{%4,%5,%6,%7},{%8,%9},{%0,%1,%2,%3};"
        : "+f"(c[0]), "+f"(c[1]), "+f"(c[2]), "+f"(c[3])
        : "r"(a0), "r"(a1), "r"(a2), "r"(a3), "r"(b0), "r"(b1));
}

// ldmatrix x4 of a 16x16 fp16 tile at (row0, k0), row stride S halves.
__device__ __forceinline__ void ldsm16x16(const __half* tile, int S, int lane, uint32_t* r) {
    const int t = lane >> 3, j = lane & 7;
    const __half* addr = tile + (size_t)(((t & 1) << 3) + j) * S + ((t >> 1) << 3);
    uint32_t a = (uint32_t)__cvta_generic_to_shared(addr);
    asm volatile("ldmatrix.sync.aligned.m8n8.x4.shared.b16 {%0,%1,%2,%3}, [%4];"
                 : "=r"(r[0]), "=r"(r[1]), "=r"(r[2]), "=r"(r[3]) : "r"(a));
}

// pack 16 fp32 (4 float4) -> 2 uint4 of halves, store to smem row
__device__ __forceinline__ void cvt_sts16(__half* dst, const float4* v) {
    uint4 w0, w1;
    w0.x = f2h2(v[0].x, v[0].y); w0.y = f2h2(v[0].z, v[0].w);
    w0.z = f2h2(v[1].x, v[1].y); w0.w = f2h2(v[1].z, v[1].w);
    w1.x = f2h2(v[2].x, v[2].y); w1.y = f2h2(v[2].z, v[2].w);
    w1.z = f2h2(v[3].x, v[3].y); w1.w = f2h2(v[3].z, v[3].w);
    *(uint4*)(dst)     = w0;
    *(uint4*)(dst + 8) = w1;
}
__device__ __forceinline__ void ldg4x4(float4* t, const float* src) {
    t[0] = *(const float4*)(src);      t[1] = *(const float4*)(src + 4);
    t[2] = *(const float4*)(src + 8);  t[3] = *(const float4*)(src + 12);
}

// ===========================================================================
// K0: W[R][C] fp32  ->  WT[C][R] fp16
// ===========================================================================
__global__ __launch_bounds__(256)
void transpose_w_kernel(const float* __restrict__ W, __half* __restrict__ WT,
                        int R, int C)
{
    __shared__ __half ts[32][33];
    const int tid = threadIdx.x;
    const int r = tid >> 3, c4 = (tid & 7) * 4;
    const float* src = W + (size_t)(blockIdx.y*32 + r)*C + blockIdx.x*32 + c4;
    const float4 v = *(const float4*)src;
    ts[c4+0][r] = __float2half(v.x);
    ts[c4+1][r] = __float2half(v.y);
    ts[c4+2][r] = __float2half(v.z);
    ts[c4+3][r] = __float2half(v.w);
    __syncthreads();
    __half* dst = WT + (size_t)(blockIdx.x*32 + r)*R + blockIdx.y*32 + c4;
    dst[0] = ts[r][c4+0]; dst[1] = ts[r][c4+1];
    dst[2] = ts[r][c4+2]; dst[3] = ts[r][c4+3];
}

// ===========================================================================
// K1: fused k/v projection (mma, 3-stage single-sync pipeline) + KV/Ksum.
// Block = (bh, chunk of 512 tokens), 256 threads (8 warps), 2 blocks/SM.
// Dynamic smem: 61440 B (3 stages / kT-vT union).
// ===========================================================================
#define SX1 40
#define SKT 136

struct K1Stage { __half Xs[128][SX1]; __half Wt[128][SX1]; };   // 20480 B
struct K1B     { __half kT[64][SKT];  __half vT[64][SKT];  };   // 34816 B
union  K1U     { K1Stage s[3]; K1B b; };                        // 61440 B
#define K1_SMEM (sizeof(K1U))

__global__ __launch_bounds__(256, 2)
void kv_build_kernel(const float* __restrict__ x)
{
    extern __shared__ char smem_raw[];
    K1U& u = *reinterpret_cast<K1U*>(smem_raw);
    __shared__ float red[256];

    const int bh = blockIdx.x, chunk = blockIdx.y;
    const int tid = threadIdx.x, lane = tid & 31, warp = tid >> 5;
    const int g = lane >> 2, tig = lane & 3;
    const int b = bh >> 3, h = bh & 7;

    const int pm0 = (warp >> 1) * 32;      // proj warp grid 4x2
    const int pni = warp & 1;
    const int pn0 = pni * 64;
    const int kd0 = (warp >> 2) * 32;      // KV warp grid 2x4
    const int ke0 = (warp & 3) * 16;

    float kvacc[2][2][4] = {};
    float ksum = 0.0f;

    const float* xb = x + ((size_t)b*SEQ + chunk*512) * CDIM;
    const int srow = tid >> 1, sside = (tid & 1) * 16;
    const int wgn = (srow < 64) ? (512 + h*64 + srow) : (1024 + h*64 + (srow - 64));
    const __half* wrow = g_WqkvT[wgn];

    for (int st = 0; st < 4; st++) {
        float cacc[2][8][4] = {};
        const float* xrow = xb + (size_t)(st*128 + srow)*CDIM + sside;

        // prologue: stages 0,1 staged directly; xr holds chunk 2
        float4 xr[4];
        ldg4x4(xr, xrow);
        cvt_sts16(&u.s[0].Xs[srow][sside], xr);
        cp16(&u.s[0].Wt[srow][sside],     wrow + sside);
        cp16(&u.s[0].Wt[srow][sside + 8], wrow + sside + 8);
        cp_commit();
        ldg4x4(xr, xrow + 32);
        cvt_sts16(&u.s[1].Xs[srow][sside], xr);
        cp16(&u.s[1].Wt[srow][sside],     wrow + 32 + sside);
        cp16(&u.s[1].Wt[srow][sside + 8], wrow + 32 + sside + 8);
        cp_commit();
        ldg4x4(xr, xrow + 64);

        for (int kc = 0; kc < 16; kc++) {
            const int cur = kc % 3;
            if (kc < 15) cp_wait1(); else cp_wait0();
            __syncthreads();
            if (kc + 2 < 16) {
                const int nx = (kc + 2) % 3;
                cvt_sts16(&u.s[nx].Xs[srow][sside], xr);
                const __half* wsrc = wrow + (kc+2)*32 + sside;
                cp16(&u.s[nx].Wt[srow][sside],     wsrc);
                cp16(&u.s[nx].Wt[srow][sside + 8], wsrc + 8);
                cp_commit();
            }
            if (kc + 3 < 16) ldg4x4(xr, xrow + (kc+3)*32);
            #pragma unroll
            for (int kh = 0; kh < 2; kh++) {
                uint32_t af[2][4], bq[4][4];
                #pragma unroll
                for (int mt = 0; mt < 2; mt++)
                    ldsm16x16(&u.s[cur].Xs[pm0 + mt*16][kh*16], SX1, lane, af[mt]);
                #pragma unroll
                for (int np = 0; np < 4; np++)
                    ldsm16x16(&u.s[cur].Wt[pn0 + np*16][kh*16], SX1, lane, bq[np]);
                #pragma unroll
                for (int mt = 0; mt < 2; mt++)
                    #pragma unroll
                    for (int nt = 0; nt < 8; nt++)
                        mma16816(cacc[mt][nt],
                                 af[mt][0], af[mt][1], af[mt][2], af[mt][3],
                                 bq[nt>>1][nt&1], bq[nt>>1][2 + (nt&1)]);
            }
        }
        __syncthreads();   // all mma done before epilogue overwrites stages (union)

        // epilogue: phi + transposed fp16 store into kT/vT (aliases stages)
        #pragma unroll
        for (int mt = 0; mt < 2; mt++) {
            const int r0 = pm0 + mt*16 + g;
            #pragma unroll
            for (int nt = 0; nt < 8; nt++) {
                const int c = pn0 + nt*8 + tig*2;
                const float* cc = cacc[mt][nt];
                if (pni == 0) {
                    u.b.kT[c+0][r0]   = __float2half(phi_map(cc[0]));
                    u.b.kT[c+1][r0]   = __float2half(phi_map(cc[1]));
                    u.b.kT[c+0][r0+8] = __float2half(phi_map(cc[2]));
                    u.b.kT[c+1][r0+8] = __float2half(phi_map(cc[3]));
                } else {
                    const int e = c - 64;
                    u.b.vT[e+0][r0]   = __float2half(cc[0]);
                    u.b.vT[e+1][r0]   = __float2half(cc[1]);
                    u.b.vT[e+0][r0+8] = __float2half(cc[2]);
                    u.b.vT[e+1][r0+8] = __float2half(cc[3]);
                }
            }
        }
        __syncthreads();
        {   // Ksum distributed over 256 threads
            const int d = tid & 63, part = tid >> 6;
            float s = 0.0f;
            #pragma unroll
            for (int n = 0; n < 32; n++) s += __half2float(u.b.kT[d][part*32 + n]);
            ksum += s;
        }
        // KV += kT[64 x 128] @ vT^T
        #pragma unroll
        for (int ks = 0; ks < 8; ks++) {
            uint32_t af[2][4], bq[4];
            #pragma unroll
            for (int mt = 0; mt < 2; mt++)
                ldsm16x16(&u.b.kT[kd0 + mt*16][ks*16], SKT, lane, af[mt]);
            ldsm16x16(&u.b.vT[ke0][ks*16], SKT, lane, bq);
            #pragma unroll
            for (int mt = 0; mt < 2; mt++)
                #pragma unroll
                for (int nt = 0; nt < 2; nt++)
                    mma16816(kvacc[mt][nt],
                             af[mt][0], af[mt][1], af[mt][2], af[mt][3],
                             bq[nt], bq[2 + nt]);
        }
        __syncthreads();
    }
    // write partials
    #pragma unroll
    for (int mt = 0; mt < 2; mt++) {
        const int d = kd0 + mt*16 + g;
        #pragma unroll
        for (int nt = 0; nt < 2; nt++) {
            const int e = ke0 + nt*8 + tig*2;
            g_KV_part[chunk][bh][d  ][e  ] = kvacc[mt][nt][0];
            g_KV_part[chunk][bh][d  ][e+1] = kvacc[mt][nt][1];
            g_KV_part[chunk][bh][d+8][e  ] = kvacc[mt][nt][2];
            g_KV_part[chunk][bh][d+8][e+1] = kvacc[mt][nt][3];
        }
    }
    red[tid] = ksum;
    __syncthreads();
    if (tid < 64)
        g_Ksum_part[chunk][bh][tid] = red[tid] + red[tid+64] + red[tid+128] + red[tid+192];
}

// ===========================================================================
// K2: reduce partials
// ===========================================================================
__global__ __launch_bounds__(256)
void kv_reduce_kernel()
{
    const int idx = blockIdx.x * 256 + threadIdx.x;
    if (idx < NBH*HD*HD) {
        const int bh = idx >> 12, r = idx & 4095;
        float s = 0.0f;
        #pragma unroll
        for (int p = 0; p < KVCH; p++) s += (&g_KV_part[p][bh][0][0])[r];
        (&g_KV[bh][0][0])[r] = s;
    }
    if (idx < NBH*HD) {
        const int bh = idx >> 6, d = idx & 63;
        float s = 0.0f;
        #pragma unroll
        for (int p = 0; p < KVCH; p++) s += g_Ksum_part[p][bh][d];
        g_Ksum[bh][d] = s;
    }
}

// ===========================================================================
// K3: q projection 128x128 (3-stage single-sync) + per-head attn.
// Grid (4 col-tiles fastest, 256 token-blocks). 256 threads, 2 blocks/SM.
// Dynamic smem: 61440 B.
// ===========================================================================
#define SX3 40
#define SQ3 136
#define SKV 72

struct K3Stage { __half Xs[128][SX3]; __half Wt[128][SX3]; };   // 20480 B
struct K3B { __half qs[128][SQ3]; __half KVt[64][SKV];
             float kss[64]; float den[128]; };                  // 44800 B
union  K3U { K3Stage s[3]; K3B b; };                            // 61440 B
#define K3_SMEM (sizeof(K3U))

__global__ __launch_bounds__(256, 2)
void q_attn_kernel(const float* __restrict__ x)
{
    extern __shared__ char smem_raw[];
    K3U& u = *reinterpret_cast<K3U*>(smem_raw);

    const int cy = blockIdx.x;             // 0..3: q col-tile (heads 2cy, 2cy+1)
    const int brow = blockIdx.y;           // 0..255 token-block
    const int tid = threadIdx.x, lane = tid & 31, warp = tid >> 5;
    const int g = lane >> 2, tig = lane & 3;
    const int bb = brow >> 5;
    const int bh_base = bb*NH + cy*2;

    const int m0 = (warp >> 1) * 32;
    const int pni = warp & 1;
    const int n0w = pni * 64;

    const int srow = tid >> 1, sside = (tid & 1) * 16;
    const float* xrow = x + ((size_t)(brow*128 + srow))*CDIM + sside;
    const __half* wrow = g_WqkvT[cy*128 + srow];

    // ---- Phase 1: q projection 128x128, K=512, 3-stage single-sync ----
    float cacc[2][8][4] = {};
    float4 xr[4];
    ldg4x4(xr, xrow);
    cvt_sts16(&u.s[0].Xs[srow][sside], xr);
    cp16(&u.s[0].Wt[srow][sside],     wrow + sside);
    cp16(&u.s[0].Wt[srow][sside + 8], wrow + sside + 8);
    cp_commit();
    ldg4x4(xr, xrow + 32);
    cvt_sts16(&u.s[1].Xs[srow][sside], xr);
    cp16(&u.s[1].Wt[srow][sside],     wrow + 32 + sside);
    cp16(&u.s[1].Wt[srow][sside + 8], wrow + 32 + sside + 8);
    cp_commit();
    ldg4x4(xr, xrow + 64);

    for (int kc = 0; kc < 16; kc++) {
        const int cur = kc % 3;
        if (kc < 15) cp_wait1(); else cp_wait0();
        __syncthreads();
        if (kc + 2 < 16) {
            const int nx = (kc + 2) % 3;
            cvt_sts16(&u.s[nx].Xs[srow][sside], xr);
            const __half* wsrc = wrow + (kc+2)*32 + sside;
            cp16(&u.s[nx].Wt[srow][sside],     wsrc);
            cp16(&u.s[nx].Wt[srow][sside + 8], wsrc + 8);
            cp_commit();
        }
        if (kc + 3 < 16) ldg4x4(xr, xrow + (kc+3)*32);
        #pragma unroll
        for (int kh = 0; kh < 2; kh++) {
            uint32_t af[2][4], bq[4][4];
            #pragma unroll
            for (int mt = 0; mt < 2; mt++)
                ldsm16x16(&u.s[cur].Xs[m0 + mt*16][kh*16], SX3, lane, af[mt]);
            #pragma unroll
            for (int np = 0; np < 4; np++)
                ldsm16x16(&u.s[cur].Wt[n0w + np*16][kh*16], SX3, lane, bq[np]);
            #pragma unroll
            for (int mt = 0; mt < 2; mt++)
                #pragma unroll
                for (int nt = 0; nt < 8; nt++)
                    mma16816(cacc[mt][nt],
                             af[mt][0], af[mt][1], af[mt][2], af[mt][3],
                             bq[nt>>1][nt&1], bq[nt>>1][2 + (nt&1)]);
        }
    }
    __syncthreads();   // mma done before phase-2 overwrites stages (union)

    // ---- Phase 2: phi -> qs (all 128 cols) ----
    #pragma unroll
    for (int mt = 0; mt < 2; mt++) {
        const int r0 = m0 + mt*16 + g;
        #pragma unroll
        for (int nt = 0; nt < 8; nt++) {
            const int c = n0w + nt*8 + tig*2;
            const float* cc = cacc[mt][nt];
            u.b.qs[r0  ][c  ] = __float2half(phi_map(cc[0]));
            u.b.qs[r0  ][c+1] = __float2half(phi_map(cc[1]));
            u.b.qs[r0+8][c  ] = __float2half(phi_map(cc[2]));
            u.b.qs[r0+8][c+1] = __float2half(phi_map(cc[3]));
        }
    }

    // ---- Phase 3: per-head attn ----
    #pragma unroll
    for (int hh = 0; hh < 2; hh++) {
        const int bh = bh_base + hh;
        const int h  = cy*2 + hh;
        if (hh == 0) __syncthreads();     // qs visible before any reads
        #pragma unroll
        for (int i = 0; i < 16; i++) {
            const int lin = tid*16 + i;
            const int d = lin >> 6, e = lin & 63;
            u.b.KVt[e][d] = __float2half(g_KV[bh][d][e]);
        }
        if (tid < 64) u.b.kss[tid] = g_Ksum[bh][tid];
        __syncthreads();
        if (tid < 128) {
            float s = 0.0f;
            #pragma unroll
            for (int d = 0; d < 64; d++)
                s += __half2float(u.b.qs[tid][hh*64 + d]) * u.b.kss[d];
            u.b.den[tid] = s;
        }
        __syncthreads();
        float oacc[2][4][4] = {};
        #pragma unroll
        for (int ks = 0; ks < 4; ks++) {
            uint32_t af[2][4], bq[2][4];
            #pragma unroll
            for (int mt = 0; mt < 2; mt++)
                ldsm16x16(&u.b.qs[m0 + mt*16][hh*64 + ks*16], SQ3, lane, af[mt]);
            #pragma unroll
            for (int np = 0; np < 2; np++)
                ldsm16x16(&u.b.KVt[pni*32 + np*16][ks*16], SKV, lane, bq[np]);
            #pragma unroll
            for (int mt = 0; mt < 2; mt++)
                #pragma unroll
                for (int nt = 0; nt < 4; nt++)
                    mma16816(oacc[mt][nt],
                             af[mt][0], af[mt][1], af[mt][2], af[mt][3],
                             bq[nt>>1][nt&1], bq[nt>>1][2 + (nt&1)]);
        }
        #pragma unroll
        for (int mt = 0; mt < 2; mt++) {
            const int r0 = m0 + mt*16 + g;
            const float inv0 = 1.0f / (u.b.den[r0]   + 1e-6f);
            const float inv1 = 1.0f / (u.b.den[r0+8] + 1e-6f);
            const size_t row0 = (size_t)(brow*128 + r0);
            #pragma unroll
            for (int nt = 0; nt < 4; nt++) {
                const int c = pni*32 + nt*8 + tig*2;
                const float* cc = oacc[mt][nt];
                __half2* d0p = (__half2*)&g_attnh[row0*CDIM + h*64 + c];
                __half2* d1p = (__half2*)&g_attnh[(row0+8)*CDIM + h*64 + c];
                *d0p = __floats2half2_rn(cc[0]*inv0, cc[1]*inv0);
                *d1p = __floats2half2_rn(cc[2]*inv1, cc[3]*inv1);
            }
        }
        if (hh == 0) __syncthreads();     // before restaging KVt/kss/den
    }
}

// ===========================================================================
// K4: out = attnh(fp16) @ W_out + bias -- 3-stage single-sync cp.async.
// Grid (4 col-tiles fastest, 256 row-tiles). 2 blocks/SM. Dynamic smem 61440.
// ===========================================================================
#define SX4 40

struct K4Stage { __half Xs[128][SX4]; __half Wt[128][SX4]; };   // 20480 B
#define K4_SMEM (3 * sizeof(K4Stage))

__global__ __launch_bounds__(256, 2)
void out_proj_kernel(const float* __restrict__ bias,
                     float* __restrict__ Cout)
{
    extern __shared__ char smem_raw[];
    K4Stage* s = reinterpret_cast<K4Stage*>(smem_raw);

    const int tid = threadIdx.x, lane = tid & 31, warp = tid >> 5;
    const int g = lane >> 2, tig = lane & 3;
    const int bcol = blockIdx.x, brow = blockIdx.y;
    const int m0 = (warp >> 1) * 32;
    const int n0w = (warp & 1) * 64;
    const int srow = tid >> 1, sside = (tid & 1) * 16;

    const __half* arow = g_attnh + (size_t)(brow*128 + srow)*CDIM + sside;
    const __half* wrow = &g_WoutT[bcol*128 + srow][sside];

    // prologue: stages 0,1
    cp16(&s[0].Xs[srow][sside],     arow);
    cp16(&s[0].Xs[srow][sside + 8], arow + 8);
    cp16(&s[0].Wt[srow][sside],     wrow);
    cp16(&s[0].Wt[srow][sside + 8], wrow + 8);
    cp_commit();
    cp16(&s[1].Xs[srow][sside],     arow + 32);
    cp16(&s[1].Xs[srow][sside + 8], arow + 40);
    cp16(&s[1].Wt[srow][sside],     wrow + 32);
    cp16(&s[1].Wt[srow][sside + 8], wrow + 40);
    cp_commit();

    float cacc[2][8][4] = {};
    for (int kc = 0; kc < 16; kc++) {
        const int cur = kc % 3;
        if (kc < 15) cp_wait1(); else cp_wait0();
        __syncthreads();
        if (kc + 2 < 16) {
            const int nx = (kc + 2) % 3;
            const __half* an = arow + (kc+2)*32;
            const __half* wn = wrow + (kc+2)*32;
            cp16(&s[nx].Xs[srow][sside],     an);
            cp16(&s[nx].Xs[srow][sside + 8], an + 8);
            cp16(&s[nx].Wt[srow][sside],     wn);
            cp16(&s[nx].Wt[srow][sside + 8], wn + 8);
            cp_commit();
        }
        #pragma unroll
        for (int kh = 0; kh < 2; kh++) {
            uint32_t af[2][4], bq[4][4];
            #pragma unroll
            for (int mt = 0; mt < 2; mt++)
                ldsm16x16(&s[cur].Xs[m0 + mt*16][kh*16], SX4, lane, af[mt]);
            #pragma unroll
            for (int np = 0; np < 4; np++)
                ldsm16x16(&s[cur].Wt[n0w + np*16][kh*16], SX4, lane, bq[np]);
            #pragma unroll
            for (int mt = 0; mt < 2; mt++)
                #pragma unroll
                for (int nt = 0; nt < 8; nt++)
                    mma16816(cacc[mt][nt],
                             af[mt][0], af[mt][1], af[mt][2], af[mt][3],
                             bq[nt>>1][nt&1], bq[nt>>1][2 + (nt&1)]);
        }
    }
    #pragma unroll
    for (int mt = 0; mt < 2; mt++) {
        const int r0 = brow*128 + m0 + mt*16 + g;
        #pragma unroll
        for (int nt = 0; nt < 8; nt++) {
            const int c = bcol*128 + n0w + nt*8 + tig*2;
            const float2 bv = *(const float2*)&bias[c];
            const float* cc = cacc[mt][nt];
            float2 o0 = { cc[0] + bv.x, cc[1] + bv.y };
            float2 o1 = { cc[2] + bv.x, cc[3] + bv.y };
            *(float2*)&Cout[(size_t)r0*CDIM + c]     = o0;
            *(float2*)&Cout[(size_t)(r0+8)*CDIM + c] = o1;
        }
    }
}

// ===========================================================================
extern "C" void kernel_launch(void* const* d_in, const int* in_sizes, int n_in,
                              void* d_out, int out_size)
{
    const float* x     = (const float*)d_in[0];
    const float* W_qkv = (const float*)d_in[1];
    const float* W_out = (const float*)d_in[2];
    const float* b_out = (const float*)d_in[3];
    float* out = (float*)d_out;

    // allow >48KB dynamic smem (idempotent; not a stream op, graph-capture safe)
    cudaFuncSetAttribute(kv_build_kernel, cudaFuncAttributeMaxDynamicSharedMemorySize, (int)K1_SMEM);
    cudaFuncSetAttribute(q_attn_kernel,   cudaFuncAttributeMaxDynamicSharedMemorySize, (int)K3_SMEM);
    cudaFuncSetAttribute(out_proj_kernel, cudaFuncAttributeMaxDynamicSharedMemorySize, (int)K4_SMEM);

    {   __half* wqkvT = nullptr; cudaGetSymbolAddress((void**)&wqkvT, g_WqkvT);
        __half* woutT = nullptr; cudaGetSymbolAddress((void**)&woutT, g_WoutT);
        transpose_w_kernel<<<dim3(3*CDIM/32, CDIM/32), 256>>>(W_qkv, wqkvT, CDIM, 3*CDIM);
        transpose_w_kernel<<<dim3(CDIM/32, CDIM/32),   256>>>(W_out, woutT, CDIM, CDIM);
    }
    {   dim3 grid(NBH, KVCH);                 // 64 x 8
        kv_build_kernel<<<grid, 256, K1_SMEM>>>(x); }
    kv_reduce_kernel<<<(NBH*HD*HD + 255)/256, 256>>>();
    {   dim3 grid(4, MROWS/128);              // col-tile fastest -> L2 x reuse
        q_attn_kernel<<<grid, 256, K3_SMEM>>>(x); }
    {   dim3 grid(CDIM/128, MROWS/128);       // col-tile fastest -> L2 attn reuse
        out_proj_kernel<<<grid, 256, K4_SMEM>>>(b_out, out); }
}

// round 17
// speedup vs baseline: 11.2898x; 1.1225x over previous
#include <cuda_runtime.h>
#include <cuda_fp16.h>
#include <cstdint>
#include <math.h>

#define BB   8
#define SEQ  4096
#define CDIM 512
#define NH   8
#define HD   64
#define MROWS (BB*SEQ)   // 32768
#define NBH  (BB*NH)     // 64
#define KVCH 8

// ---------------- static device scratch (~76.5 MB) -------------------------
__device__ float  g_KV_part[KVCH][NBH][HD][HD];
__device__ float  g_Ksum_part[KVCH][NBH][HD];
__device__ float  g_KV[NBH][HD][HD];
__device__ float  g_Ksum[NBH][HD];
__device__ __half g_attnh[(size_t)MROWS*CDIM];    // 32 MB
__device__ __half g_xh[(size_t)MROWS*CDIM];       // 32 MB  x pre-converted fp16
__device__ __half g_WqkvT[3*CDIM][CDIM];          // 1.5 MB  [out_col][k]
__device__ __half g_WoutT[CDIM][CDIM];            // 0.5 MB  [out_col][k]

__device__ __forceinline__ float phi_map(float x) {
    return x > 0.0f ? x + 1.0f : __expf(x);
}
__device__ __forceinline__ uint32_t f2h2(float a, float b) {
    __half2 h = __floats2half2_rn(a, b);
    return *reinterpret_cast<uint32_t*>(&h);
}

// ---- cp.async helpers ------------------------------------------------------
__device__ __forceinline__ void cp16(void* dst, const void* src) {
    uint32_t d = (uint32_t)__cvta_generic_to_shared(dst);
    asm volatile("cp.async.cg.shared.global [%0], [%1], 16;" :: "r"(d), "l"(src));
}
__device__ __forceinline__ void cp_commit() { asm volatile("cp.async.commit_group;" ::: "memory"); }
__device__ __forceinline__ void cp_wait0()  { asm volatile("cp.async.wait_group 0;" ::: "memory"); }
__device__ __forceinline__ void cp_wait1()  { asm volatile("cp.async.wait_group 1;" ::: "memory"); }

// ---- mma.sync m16n8k16 fp16 -> fp32 ---------------------------------------
__device__ __forceinline__ void mma16816(float* c,
    uint32_t a0, uint32_t a1, uint32_t a2, uint32_t a3,
    uint32_t b0, uint32_t b1)
{
    asm volatile(
        "mma.sync.aligned.m16n8k16.row.col.f32.f16.f16.f32 "
        "{%0,%1,%2,%3},{%4,%5,%6,%7},{%8,%9},{%0,%1,%2,%3};"
        : "+f"(c[0]), "+f"(c[1]), "+f"(c[2]), "+f"(c[3])
        : "r"(a0), "r"(a1), "r"(a2), "r"(a3), "r"(b0), "r"(b1));
}

// ldmatrix x4 of a 16x16 fp16 tile at (row0, k0), row stride S halves.
__device__ __forceinline__ void ldsm16x16(const __half* tile, int S, int lane, uint32_t* r) {
    const int t = lane >> 3, j = lane & 7;
    const __half* addr = tile + (size_t)(((t & 1) << 3) + j) * S + ((t >> 1) << 3);
    uint32_t a = (uint32_t)__cvta_generic_to_shared(addr);
    asm volatile("ldmatrix.sync.aligned.m8n8.x4.shared.b16 {%0,%1,%2,%3}, [%4];"
                 : "=r"(r[0]), "=r"(r[1]), "=r"(r[2]), "=r"(r[3]) : "r"(a));
}

// ===========================================================================
// K0a: x fp32 -> fp16 (coalesced; 8 elems/thread)
// ===========================================================================
__global__ __launch_bounds__(256)
void cvt_x_kernel(const float* __restrict__ x)
{
    const size_t i = ((size_t)blockIdx.x * 256 + threadIdx.x) * 8;
    const float4 a = *(const float4*)(x + i);
    const float4 b = *(const float4*)(x + i + 4);
    uint4 w;
    w.x = f2h2(a.x, a.y); w.y = f2h2(a.z, a.w);
    w.z = f2h2(b.x, b.y); w.w = f2h2(b.z, b.w);
    *(uint4*)(g_xh + i) = w;
}

// ===========================================================================
// K0b: W[R][C] fp32 -> WT[C][R] fp16
// ===========================================================================
__global__ __launch_bounds__(256)
void transpose_w_kernel(const float* __restrict__ W, __half* __restrict__ WT,
                        int R, int C)
{
    __shared__ __half ts[32][33];
    const int tid = threadIdx.x;
    const int r = tid >> 3, c4 = (tid & 7) * 4;
    const float* src = W + (size_t)(blockIdx.y*32 + r)*C + blockIdx.x*32 + c4;
    const float4 v = *(const float4*)src;
    ts[c4+0][r] = __float2half(v.x);
    ts[c4+1][r] = __float2half(v.y);
    ts[c4+2][r] = __float2half(v.z);
    ts[c4+3][r] = __float2half(v.w);
    __syncthreads();
    __half* dst = WT + (size_t)(blockIdx.x*32 + r)*R + blockIdx.y*32 + c4;
    dst[0] = ts[r][c4+0]; dst[1] = ts[r][c4+1];
    dst[2] = ts[r][c4+2]; dst[3] = ts[r][c4+3];
}

// ===========================================================================
// K1: fused k/v projection + KV/Ksum. 3-stage single-sync, all cp.async.
// Block = (bh, chunk of 512 tokens), 256 threads, 2 blocks/SM. Dyn smem 61440.
// ===========================================================================
#define SX1 40
#define SKT 136

struct K1Stage { __half Xs[128][SX1]; __half Wt[128][SX1]; };   // 20480 B
struct K1B     { __half kT[64][SKT];  __half vT[64][SKT];  };   // 34816 B
union  K1U     { K1Stage s[3]; K1B b; };                        // 61440 B
#define K1_SMEM (sizeof(K1U))

__global__ __launch_bounds__(256, 2)
void kv_build_kernel()
{
    extern __shared__ char smem_raw[];
    K1U& u = *reinterpret_cast<K1U*>(smem_raw);
    __shared__ float red[256];

    const int bh = blockIdx.x, chunk = blockIdx.y;
    const int tid = threadIdx.x, lane = tid & 31, warp = tid >> 5;
    const int g = lane >> 2, tig = lane & 3;
    const int b = bh >> 3, h = bh & 7;

    const int pm0 = (warp >> 1) * 32;      // proj warp grid 4x2
    const int pni = warp & 1;
    const int pn0 = pni * 64;
    const int kd0 = (warp >> 2) * 32;      // KV warp grid 2x4
    const int ke0 = (warp & 3) * 16;

    float kvacc[2][2][4] = {};
    float ksum = 0.0f;

    const int srow = tid >> 1, sside = (tid & 1) * 16;     // halves
    const int wgn = (srow < 64) ? (512 + h*64 + srow) : (1024 + h*64 + (srow - 64));
    const __half* wrow = g_WqkvT[wgn];
    const __half* xbase = g_xh + ((size_t)b*SEQ + chunk*512) * CDIM;

    for (int st = 0; st < 4; st++) {
        float cacc[2][8][4] = {};
        const __half* xrow = xbase + (size_t)(st*128 + srow)*CDIM + sside;

        // prologue: stages 0,1 via cp.async
        #pragma unroll
        for (int p = 0; p < 2; p++) {
            cp16(&u.s[p].Xs[srow][sside],     xrow + p*32);
            cp16(&u.s[p].Xs[srow][sside + 8], xrow + p*32 + 8);
            cp16(&u.s[p].Wt[srow][sside],     wrow + p*32 + sside);
            cp16(&u.s[p].Wt[srow][sside + 8], wrow + p*32 + sside + 8);
            cp_commit();
        }

        for (int kc = 0; kc < 16; kc++) {
            const int cur = kc % 3;
            if (kc < 15) cp_wait1(); else cp_wait0();
            __syncthreads();
            if (kc + 2 < 16) {
                const int nx = (kc + 2) % 3;
                cp16(&u.s[nx].Xs[srow][sside],     xrow + (kc+2)*32);
                cp16(&u.s[nx].Xs[srow][sside + 8], xrow + (kc+2)*32 + 8);
                cp16(&u.s[nx].Wt[srow][sside],     wrow + (kc+2)*32 + sside);
                cp16(&u.s[nx].Wt[srow][sside + 8], wrow + (kc+2)*32 + sside + 8);
                cp_commit();
            }
            #pragma unroll
            for (int kh = 0; kh < 2; kh++) {
                uint32_t af[2][4], bq[4][4];
                #pragma unroll
                for (int mt = 0; mt < 2; mt++)
                    ldsm16x16(&u.s[cur].Xs[pm0 + mt*16][kh*16], SX1, lane, af[mt]);
                #pragma unroll
                for (int np = 0; np < 4; np++)
                    ldsm16x16(&u.s[cur].Wt[pn0 + np*16][kh*16], SX1, lane, bq[np]);
                #pragma unroll
                for (int mt = 0; mt < 2; mt++)
                    #pragma unroll
                    for (int nt = 0; nt < 8; nt++)
                        mma16816(cacc[mt][nt],
                                 af[mt][0], af[mt][1], af[mt][2], af[mt][3],
                                 bq[nt>>1][nt&1], bq[nt>>1][2 + (nt&1)]);
            }
        }
        __syncthreads();   // all mma done before epilogue overwrites stages (union)

        // epilogue: phi + transposed fp16 store into kT/vT (aliases stages)
        #pragma unroll
        for (int mt = 0; mt < 2; mt++) {
            const int r0 = pm0 + mt*16 + g;
            #pragma unroll
            for (int nt = 0; nt < 8; nt++) {
                const int c = pn0 + nt*8 + tig*2;
                const float* cc = cacc[mt][nt];
                if (pni == 0) {
                    u.b.kT[c+0][r0]   = __float2half(phi_map(cc[0]));
                    u.b.kT[c+1][r0]   = __float2half(phi_map(cc[1]));
                    u.b.kT[c+0][r0+8] = __float2half(phi_map(cc[2]));
                    u.b.kT[c+1][r0+8] = __float2half(phi_map(cc[3]));
                } else {
                    const int e = c - 64;
                    u.b.vT[e+0][r0]   = __float2half(cc[0]);
                    u.b.vT[e+1][r0]   = __float2half(cc[1]);
                    u.b.vT[e+0][r0+8] = __float2half(cc[2]);
                    u.b.vT[e+1][r0+8] = __float2half(cc[3]);
                }
            }
        }
        __syncthreads();
        {   // Ksum distributed over 256 threads
            const int d = tid & 63, part = tid >> 6;
            float s = 0.0f;
            #pragma unroll
            for (int n = 0; n < 32; n++) s += __half2float(u.b.kT[d][part*32 + n]);
            ksum += s;
        }
        // KV += kT[64 x 128] @ vT^T
        #pragma unroll
        for (int ks = 0; ks < 8; ks++) {
            uint32_t af[2][4], bq[4];
            #pragma unroll
            for (int mt = 0; mt < 2; mt++)
                ldsm16x16(&u.b.kT[kd0 + mt*16][ks*16], SKT, lane, af[mt]);
            ldsm16x16(&u.b.vT[ke0][ks*16], SKT, lane, bq);
            #pragma unroll
            for (int mt = 0; mt < 2; mt++)
                #pragma unroll
                for (int nt = 0; nt < 2; nt++)
                    mma16816(kvacc[mt][nt],
                             af[mt][0], af[mt][1], af[mt][2], af[mt][3],
                             bq[nt], bq[2 + nt]);
        }
        __syncthreads();
    }
    // write partials
    #pragma unroll
    for (int mt = 0; mt < 2; mt++) {
        const int d = kd0 + mt*16 + g;
        #pragma unroll
        for (int nt = 0; nt < 2; nt++) {
            const int e = ke0 + nt*8 + tig*2;
            g_KV_part[chunk][bh][d  ][e  ] = kvacc[mt][nt][0];
            g_KV_part[chunk][bh][d  ][e+1] = kvacc[mt][nt][1];
            g_KV_part[chunk][bh][d+8][e  ] = kvacc[mt][nt][2];
            g_KV_part[chunk][bh][d+8][e+1] = kvacc[mt][nt][3];
        }
    }
    red[tid] = ksum;
    __syncthreads();
    if (tid < 64)
        g_Ksum_part[chunk][bh][tid] = red[tid] + red[tid+64] + red[tid+128] + red[tid+192];
}

// ===========================================================================
// K2: reduce partials
// ===========================================================================
__global__ __launch_bounds__(256)
void kv_reduce_kernel()
{
    const int idx = blockIdx.x * 256 + threadIdx.x;
    if (idx < NBH*HD*HD) {
        const int bh = idx >> 12, r = idx & 4095;
        float s = 0.0f;
        #pragma unroll
        for (int p = 0; p < KVCH; p++) s += (&g_KV_part[p][bh][0][0])[r];
        (&g_KV[bh][0][0])[r] = s;
    }
    if (idx < NBH*HD) {
        const int bh = idx >> 6, d = idx & 63;
        float s = 0.0f;
        #pragma unroll
        for (int p = 0; p < KVCH; p++) s += g_Ksum_part[p][bh][d];
        g_Ksum[bh][d] = s;
    }
}

// ===========================================================================
// K3: q projection 128x128 (3-stage single-sync, all cp.async) + per-head attn.
// Grid (4 col-tiles fastest, 256 token-blocks). 256 threads, 2 blocks/SM.
// ===========================================================================
#define SX3 40
#define SQ3 136
#define SKV 72

struct K3Stage { __half Xs[128][SX3]; __half Wt[128][SX3]; };   // 20480 B
struct K3B { __half qs[128][SQ3]; __half KVt[64][SKV];
             float kss[64]; float den[128]; };                  // 44800 B
union  K3U { K3Stage s[3]; K3B b; };                            // 61440 B
#define K3_SMEM (sizeof(K3U))

__global__ __launch_bounds__(256, 2)
void q_attn_kernel()
{
    extern __shared__ char smem_raw[];
    K3U& u = *reinterpret_cast<K3U*>(smem_raw);

    const int cy = blockIdx.x;             // 0..3: q col-tile (heads 2cy, 2cy+1)
    const int brow = blockIdx.y;           // 0..255 token-block
    const int tid = threadIdx.x, lane = tid & 31, warp = tid >> 5;
    const int g = lane >> 2, tig = lane & 3;
    const int bb = brow >> 5;
    const int bh_base = bb*NH + cy*2;

    const int m0 = (warp >> 1) * 32;
    const int pni = warp & 1;
    const int n0w = pni * 64;

    const int srow = tid >> 1, sside = (tid & 1) * 16;
    const __half* xrow = g_xh + ((size_t)(brow*128 + srow))*CDIM + sside;
    const __half* wrow = g_WqkvT[cy*128 + srow];

    // ---- Phase 1: q projection 128x128, K=512, 3-stage single-sync ----
    float cacc[2][8][4] = {};
    #pragma unroll
    for (int p = 0; p < 2; p++) {
        cp16(&u.s[p].Xs[srow][sside],     xrow + p*32);
        cp16(&u.s[p].Xs[srow][sside + 8], xrow + p*32 + 8);
        cp16(&u.s[p].Wt[srow][sside],     wrow + p*32 + sside);
        cp16(&u.s[p].Wt[srow][sside + 8], wrow + p*32 + sside + 8);
        cp_commit();
    }

    for (int kc = 0; kc < 16; kc++) {
        const int cur = kc % 3;
        if (kc < 15) cp_wait1(); else cp_wait0();
        __syncthreads();
        if (kc + 2 < 16) {
            const int nx = (kc + 2) % 3;
            cp16(&u.s[nx].Xs[srow][sside],     xrow + (kc+2)*32);
            cp16(&u.s[nx].Xs[srow][sside + 8], xrow + (kc+2)*32 + 8);
            cp16(&u.s[nx].Wt[srow][sside],     wrow + (kc+2)*32 + sside);
            cp16(&u.s[nx].Wt[srow][sside + 8], wrow + (kc+2)*32 + sside + 8);
            cp_commit();
        }
        #pragma unroll
        for (int kh = 0; kh < 2; kh++) {
            uint32_t af[2][4], bq[4][4];
            #pragma unroll
            for (int mt = 0; mt < 2; mt++)
                ldsm16x16(&u.s[cur].Xs[m0 + mt*16][kh*16], SX3, lane, af[mt]);
            #pragma unroll
            for (int np = 0; np < 4; np++)
                ldsm16x16(&u.s[cur].Wt[n0w + np*16][kh*16], SX3, lane, bq[np]);
            #pragma unroll
            for (int mt = 0; mt < 2; mt++)
                #pragma unroll
                for (int nt = 0; nt < 8; nt++)
                    mma16816(cacc[mt][nt],
                             af[mt][0], af[mt][1], af[mt][2], af[mt][3],
                             bq[nt>>1][nt&1], bq[nt>>1][2 + (nt&1)]);
        }
    }
    __syncthreads();   // mma done before phase-2 overwrites stages (union)

    // ---- Phase 2: phi -> qs (all 128 cols) ----
    #pragma unroll
    for (int mt = 0; mt < 2; mt++) {
        const int r0 = m0 + mt*16 + g;
        #pragma unroll
        for (int nt = 0; nt < 8; nt++) {
            const int c = n0w + nt*8 + tig*2;
            const float* cc = cacc[mt][nt];
            u.b.qs[r0  ][c  ] = __float2half(phi_map(cc[0]));
            u.b.qs[r0  ][c+1] = __float2half(phi_map(cc[1]));
            u.b.qs[r0+8][c  ] = __float2half(phi_map(cc[2]));
            u.b.qs[r0+8][c+1] = __float2half(phi_map(cc[3]));
        }
    }

    // ---- Phase 3: per-head attn ----
    #pragma unroll
    for (int hh = 0; hh < 2; hh++) {
        const int bh = bh_base + hh;
        const int h  = cy*2 + hh;
        if (hh == 0) __syncthreads();     // qs visible before any reads
        #pragma unroll
        for (int i = 0; i < 16; i++) {
            const int lin = tid*16 + i;
            const int d = lin >> 6, e = lin & 63;
            u.b.KVt[e][d] = __float2half(g_KV[bh][d][e]);
        }
        if (tid < 64) u.b.kss[tid] = g_Ksum[bh][tid];
        __syncthreads();
        if (tid < 128) {
            float s = 0.0f;
            #pragma unroll
            for (int d = 0; d < 64; d++)
                s += __half2float(u.b.qs[tid][hh*64 + d]) * u.b.kss[d];
            u.b.den[tid] = s;
        }
        __syncthreads();
        float oacc[2][4][4] = {};
        #pragma unroll
        for (int ks = 0; ks < 4; ks++) {
            uint32_t af[2][4], bq[2][4];
            #pragma unroll
            for (int mt = 0; mt < 2; mt++)
                ldsm16x16(&u.b.qs[m0 + mt*16][hh*64 + ks*16], SQ3, lane, af[mt]);
            #pragma unroll
            for (int np = 0; np < 2; np++)
                ldsm16x16(&u.b.KVt[pni*32 + np*16][ks*16], SKV, lane, bq[np]);
            #pragma unroll
            for (int mt = 0; mt < 2; mt++)
                #pragma unroll
                for (int nt = 0; nt < 4; nt++)
                    mma16816(oacc[mt][nt],
                             af[mt][0], af[mt][1], af[mt][2], af[mt][3],
                             bq[nt>>1][nt&1], bq[nt>>1][2 + (nt&1)]);
        }
        #pragma unroll
        for (int mt = 0; mt < 2; mt++) {
            const int r0 = m0 + mt*16 + g;
            const float inv0 = 1.0f / (u.b.den[r0]   + 1e-6f);
            const float inv1 = 1.0f / (u.b.den[r0+8] + 1e-6f);
            const size_t row0 = (size_t)(brow*128 + r0);
            #pragma unroll
            for (int nt = 0; nt < 4; nt++) {
                const int c = pni*32 + nt*8 + tig*2;
                const float* cc = oacc[mt][nt];
                __half2* d0p = (__half2*)&g_attnh[row0*CDIM + h*64 + c];
                __half2* d1p = (__half2*)&g_attnh[(row0+8)*CDIM + h*64 + c];
                *d0p = __floats2half2_rn(cc[0]*inv0, cc[1]*inv0);
                *d1p = __floats2half2_rn(cc[2]*inv1, cc[3]*inv1);
            }
        }
        if (hh == 0) __syncthreads();     // before restaging KVt/kss/den
    }
}

// ===========================================================================
// K4: out = attnh(fp16) @ W_out + bias -- 3-stage single-sync cp.async.
// Grid (4 col-tiles fastest, 256 row-tiles). 2 blocks/SM. Dyn smem 61440.
// ===========================================================================
#define SX4 40

struct K4Stage { __half Xs[128][SX4]; __half Wt[128][SX4]; };   // 20480 B
#define K4_SMEM (3 * sizeof(K4Stage))

__global__ __launch_bounds__(256, 2)
void out_proj_kernel(const float* __restrict__ bias,
                     float* __restrict__ Cout)
{
    extern __shared__ char smem_raw[];
    K4Stage* s = reinterpret_cast<K4Stage*>(smem_raw);

    const int tid = threadIdx.x, lane = tid & 31, warp = tid >> 5;
    const int g = lane >> 2, tig = lane & 3;
    const int bcol = blockIdx.x, brow = blockIdx.y;
    const int m0 = (warp >> 1) * 32;
    const int n0w = (warp & 1) * 64;
    const int srow = tid >> 1, sside = (tid & 1) * 16;

    const __half* arow = g_attnh + (size_t)(brow*128 + srow)*CDIM + sside;
    const __half* wrow = &g_WoutT[bcol*128 + srow][sside];

    #pragma unroll
    for (int p = 0; p < 2; p++) {
        cp16(&s[p].Xs[srow][sside],     arow + p*32);
        cp16(&s[p].Xs[srow][sside + 8], arow + p*32 + 8);
        cp16(&s[p].Wt[srow][sside],     wrow + p*32);
        cp16(&s[p].Wt[srow][sside + 8], wrow + p*32 + 8);
        cp_commit();
    }

    float cacc[2][8][4] = {};
    for (int kc = 0; kc < 16; kc++) {
        const int cur = kc % 3;
        if (kc < 15) cp_wait1(); else cp_wait0();
        __syncthreads();
        if (kc + 2 < 16) {
            const int nx = (kc + 2) % 3;
            cp16(&s[nx].Xs[srow][sside],     arow + (kc+2)*32);
            cp16(&s[nx].Xs[srow][sside + 8], arow + (kc+2)*32 + 8);
            cp16(&s[nx].Wt[srow][sside],     wrow + (kc+2)*32);
            cp16(&s[nx].Wt[srow][sside + 8], wrow + (kc+2)*32 + 8);
            cp_commit();
        }
        #pragma unroll
        for (int kh = 0; kh < 2; kh++) {
            uint32_t af[2][4], bq[4][4];
            #pragma unroll
            for (int mt = 0; mt < 2; mt++)
                ldsm16x16(&s[cur].Xs[m0 + mt*16][kh*16], SX4, lane, af[mt]);
            #pragma unroll
            for (int np = 0; np < 4; np++)
                ldsm16x16(&s[cur].Wt[n0w + np*16][kh*16], SX4, lane, bq[np]);
            #pragma unroll
            for (int mt = 0; mt < 2; mt++)
                #pragma unroll
                for (int nt = 0; nt < 8; nt++)
                    mma16816(cacc[mt][nt],
                             af[mt][0], af[mt][1], af[mt][2], af[mt][3],
                             bq[nt>>1][nt&1], bq[nt>>1][2 + (nt&1)]);
        }
    }
    #pragma unroll
    for (int mt = 0; mt < 2; mt++) {
        const int r0 = brow*128 + m0 + mt*16 + g;
        #pragma unroll
        for (int nt = 0; nt < 8; nt++) {
            const int c = bcol*128 + n0w + nt*8 + tig*2;
            const float2 bv = *(const float2*)&bias[c];
            const float* cc = cacc[mt][nt];
            float2 o0 = { cc[0] + bv.x, cc[1] + bv.y };
            float2 o1 = { cc[2] + bv.x, cc[3] + bv.y };
            *(float2*)&Cout[(size_t)r0*CDIM + c]     = o0;
            *(float2*)&Cout[(size_t)(r0+8)*CDIM + c] = o1;
        }
    }
}

// ===========================================================================
extern "C" void kernel_launch(void* const* d_in, const int* in_sizes, int n_in,
                              void* d_out, int out_size)
{
    const float* x     = (const float*)d_in[0];
    const float* W_qkv = (const float*)d_in[1];
    const float* W_out = (const float*)d_in[2];
    const float* b_out = (const float*)d_in[3];
    float* out = (float*)d_out;

    cudaFuncSetAttribute(kv_build_kernel, cudaFuncAttributeMaxDynamicSharedMemorySize, (int)K1_SMEM);
    cudaFuncSetAttribute(q_attn_kernel,   cudaFuncAttributeMaxDynamicSharedMemorySize, (int)K3_SMEM);
    cudaFuncSetAttribute(out_proj_kernel, cudaFuncAttributeMaxDynamicSharedMemorySize, (int)K4_SMEM);

    // K0: convert inputs once
    cvt_x_kernel<<<(MROWS*CDIM)/(256*8), 256>>>(x);
    {   __half* wqkvT = nullptr; cudaGetSymbolAddress((void**)&wqkvT, g_WqkvT);
        __half* woutT = nullptr; cudaGetSymbolAddress((void**)&woutT, g_WoutT);
        transpose_w_kernel<<<dim3(3*CDIM/32, CDIM/32), 256>>>(W_qkv, wqkvT, CDIM, 3*CDIM);
        transpose_w_kernel<<<dim3(CDIM/32, CDIM/32),   256>>>(W_out, woutT, CDIM, CDIM);
    }
    {   dim3 grid(NBH, KVCH);                 // 64 x 8
        kv_build_kernel<<<grid, 256, K1_SMEM>>>(); }
    kv_reduce_kernel<<<(NBH*HD*HD + 255)/256, 256>>>();
    {   dim3 grid(4, MROWS/128);              // col-tile fastest -> L2 x reuse
        q_attn_kernel<<<grid, 256, K3_SMEM>>>(); }
    {   dim3 grid(CDIM/128, MROWS/128);       // col-tile fastest -> L2 attn reuse
        out_proj_kernel<<<grid, 256, K4_SMEM>>>(b_out, out); }
}